// round 8
// baseline (speedup 1.0000x reference)
#include <cuda_runtime.h>
#include <math.h>

// ---- problem constants ----
#define D_   2048
#define H_   16
#define KVH_ 4
#define HD_  128
#define B_   2
#define T_   2048
#define BT_  (B_*T_)          // 4096
#define QCOLS_ (H_*HD_)       // 2048
#define KCOLS_ (KVH_*HD_)     // 512
#define CAP_ 50.0f
#define SCALE_ 0.08838834764831845f  // 128^-0.5

// ---- scratch (static device arrays; no allocations allowed) ----
static __device__ float    g_q[BT_*QCOLS_];
static __device__ float    g_k[BT_*KCOLS_];
static __device__ float    g_v[BT_*KCOLS_];
static __device__ unsigned g_ot[BT_*QCOLS_];     // attention out, tf32 bits
static __device__ unsigned g_xt[BT_*D_];         // tf32 copies of GEMM operands
static __device__ unsigned g_wqt[QCOLS_*D_];
static __device__ unsigned g_wkt[KCOLS_*D_];
static __device__ unsigned g_wvt[KCOLS_*D_];
static __device__ unsigned g_wot[D_*QCOLS_];

// ============================================================================
// tf32 mma helpers
// ============================================================================
__device__ __forceinline__ unsigned f2tf32(float x) {
    unsigned u;
    asm("cvt.rna.tf32.f32 %0, %1;" : "=r"(u) : "f"(x));
    return u;
}

__device__ __forceinline__ void mma_tf32(float* c, const unsigned* a, const unsigned* b) {
    asm volatile(
        "mma.sync.aligned.m16n8k8.row.col.f32.tf32.tf32.f32 "
        "{%0,%1,%2,%3}, {%4,%5,%6,%7}, {%8,%9}, {%0,%1,%2,%3};"
        : "+f"(c[0]), "+f"(c[1]), "+f"(c[2]), "+f"(c[3])
        : "r"(a[0]), "r"(a[1]), "r"(a[2]), "r"(a[3]), "r"(b[0]), "r"(b[1]));
}

__device__ __forceinline__ float tanh_fast(float x) {
    float r;
    asm("tanh.approx.f32 %0, %1;" : "=f"(r) : "f"(x));
    return r;
}

__device__ __forceinline__ void cp_async16(void* smem_dst, const void* gsrc) {
    unsigned saddr = (unsigned)__cvta_generic_to_shared(smem_dst);
    asm volatile("cp.async.cg.shared.global [%0], [%1], 16;" :: "r"(saddr), "l"(gsrc));
}
#define CP_COMMIT() asm volatile("cp.async.commit_group;")
#define CP_WAIT0()  asm volatile("cp.async.wait_group 0;")

// ============================================================================
// Elementwise f32 -> tf32-bit conversion (grid-stride over float4 groups)
// ============================================================================
__global__ __launch_bounds__(256) void cvt_tf32_k(
    const float* __restrict__ in, unsigned* __restrict__ out, int n4)
{
    int i = blockIdx.x * 256 + threadIdx.x;
    if (i >= n4) return;
    float4 v = ((const float4*)in)[i];
    uint4 u;
    u.x = f2tf32(v.x); u.y = f2tf32(v.y);
    u.z = f2tf32(v.z); u.w = f2tf32(v.w);
    ((uint4*)out)[i] = u;
}

// ============================================================================
// tf32 tensor-core GEMM: C[M,N] = A[M,K] * B[N,K]^T. Operands are PRE-CONVERTED
// tf32 bits in global (no cvt in the loop). 128x128x32 CTA tile, 8 warps (4x2),
// warp tile 32x64, 2-stage cp.async pipeline, pad-36 rows (conflict-free).
// ============================================================================
#define BK_ 32
#define LDP_ 36
#define GEMM_SMEM (4 * 128 * LDP_ * (int)sizeof(unsigned))  // 2 stages x (A+B)

__global__ __launch_bounds__(256) void gemm_tf32(
    const unsigned* __restrict__ A, const unsigned* __restrict__ Bw,
    float* __restrict__ C, int M, int N, int K)
{
    extern __shared__ unsigned sm[];
    unsigned* AsBase = sm;                    // [2][128*LDP_]
    unsigned* BsBase = sm + 2 * 128 * LDP_;   // [2][128*LDP_]

    const int tid  = threadIdx.x;
    const int lane = tid & 31;
    const int warp = tid >> 5;
    const int wm = (warp & 3) * 32;    // warp row offset within tile
    const int wn = (warp >> 2) * 64;   // warp col offset within tile
    const int rowBase = blockIdx.y * 128;
    const int colBase = blockIdx.x * 128;

    const int lr = tid >> 3;          // load row sub-index (0..31)
    const int lc = (tid & 7) * 4;     // load col (word index, 16B steps)

    float acc[2][8][4];
#pragma unroll
    for (int mi = 0; mi < 2; mi++)
#pragma unroll
        for (int ni = 0; ni < 8; ni++)
#pragma unroll
            for (int q = 0; q < 4; q++) acc[mi][ni][q] = 0.f;

    const int ntiles = K / BK_;

    {
        unsigned* as = AsBase;
        unsigned* bs = BsBase;
#pragma unroll
        for (int it = 0; it < 4; it++) {
            int r = it * 32 + lr;
            cp_async16(as + r * LDP_ + lc, A  + (size_t)(rowBase + r) * K + lc);
            cp_async16(bs + r * LDP_ + lc, Bw + (size_t)(colBase + r) * K + lc);
        }
        CP_COMMIT();
    }

    int cur = 0;
    for (int t = 0; t < ntiles; t++) {
        CP_WAIT0();
        __syncthreads();

        if (t + 1 < ntiles) {
            int k0 = (t + 1) * BK_;
            unsigned* as = AsBase + (cur ^ 1) * 128 * LDP_;
            unsigned* bs = BsBase + (cur ^ 1) * 128 * LDP_;
#pragma unroll
            for (int it = 0; it < 4; it++) {
                int r = it * 32 + lr;
                cp_async16(as + r * LDP_ + lc, A  + (size_t)(rowBase + r) * K + k0 + lc);
                cp_async16(bs + r * LDP_ + lc, Bw + (size_t)(colBase + r) * K + k0 + lc);
            }
            CP_COMMIT();
        }

        const unsigned* as = AsBase + cur * 128 * LDP_;
        const unsigned* bs = BsBase + cur * 128 * LDP_;
#pragma unroll
        for (int kk = 0; kk < 4; kk++) {
            const int k = kk * 8 + (lane & 3);
            unsigned af[2][4], bf[8][2];
#pragma unroll
            for (int mi = 0; mi < 2; mi++) {
                int r = wm + mi * 16 + (lane >> 2);
                af[mi][0] = as[r       * LDP_ + k];
                af[mi][1] = as[(r + 8) * LDP_ + k];
                af[mi][2] = as[r       * LDP_ + k + 4];
                af[mi][3] = as[(r + 8) * LDP_ + k + 4];
            }
#pragma unroll
            for (int ni = 0; ni < 8; ni++) {
                int n = wn + ni * 8 + (lane >> 2);
                bf[ni][0] = bs[n * LDP_ + k];
                bf[ni][1] = bs[n * LDP_ + k + 4];
            }
#pragma unroll
            for (int mi = 0; mi < 2; mi++)
#pragma unroll
                for (int ni = 0; ni < 8; ni++)
                    mma_tf32(acc[mi][ni], af[mi], bf[ni]);
        }
        cur ^= 1;
    }

#pragma unroll
    for (int mi = 0; mi < 2; mi++) {
        int r0 = rowBase + wm + mi * 16 + (lane >> 2);
#pragma unroll
        for (int ni = 0; ni < 8; ni++) {
            int c0 = colBase + wn + ni * 8 + (lane & 3) * 2;
            *(float2*)&C[(size_t)r0       * N + c0] = make_float2(acc[mi][ni][0], acc[mi][ni][1]);
            *(float2*)&C[(size_t)(r0 + 8) * N + c0] = make_float2(acc[mi][ni][2], acc[mi][ni][3]);
        }
    }
}

// ============================================================================
// RMSNorm: one warp per 128-element row, in place.
// ============================================================================
__global__ __launch_bounds__(256) void rmsnorm_k(
    float* __restrict__ data, const float* __restrict__ gamma,
    int nrows, float scale)
{
    int row  = blockIdx.x * 8 + (threadIdx.x >> 5);
    int lane = threadIdx.x & 31;
    if (row >= nrows) return;
    float4 v = ((float4*)data)[(size_t)row * 32 + lane];
    float ss = v.x*v.x + v.y*v.y + v.z*v.z + v.w*v.w;
#pragma unroll
    for (int off = 16; off > 0; off >>= 1)
        ss += __shfl_xor_sync(0xffffffffu, ss, off);
    float r = rsqrtf(ss * (1.0f/128.0f) + 1e-6f) * scale;
    float4 g = ((const float4*)gamma)[lane];
    v.x *= r * g.x; v.y *= r * g.y; v.z *= r * g.z; v.w *= r * g.w;
    ((float4*)data)[(size_t)row * 32 + lane] = v;
}

// ============================================================================
// Tensor-core flash attention (R5 structure, causal, tanh softcap).
// CTA: 128 threads (4 warps). Tile: 64 q-rows x 64 k-cols, HD=128.
// Output written as tf32 BITS (feeds O-proj directly).
// ============================================================================
#define AT_LDK 132
#define AT_VROW 260
#define ATTN_SMEM ((2*64*AT_LDK + 32*AT_VROW) * (int)sizeof(unsigned))

__global__ __launch_bounds__(128) void attn_mma(
    const float* __restrict__ Q, const float* __restrict__ Kk,
    const float* __restrict__ Vv, unsigned* __restrict__ O)
{
    extern __shared__ unsigned smu[];
    unsigned* Qs = smu;
    unsigned* Ks = Qs + 64 * AT_LDK;
    unsigned* Vt = Ks + 64 * AT_LDK;

    const int tid  = threadIdx.x;
    const int lane = tid & 31;
    const int warp = tid >> 5;
    const int gid  = lane >> 2;      // group id (row within frag)
    const int m4   = lane & 3;       // thread-in-group

    const int bh = blockIdx.y;
    const int b = bh >> 4, h = bh & 15, kvh = h >> 2;
    const int qt = gridDim.x - 1 - blockIdx.x;     // heavy tiles first
    const int qBase = qt * 64;

    const float* qp = Q  + (size_t)b*T_*QCOLS_ + (size_t)h*HD_;
    const float* kp = Kk + (size_t)b*T_*KCOLS_ + (size_t)kvh*HD_;
    const float* vp = Vv + (size_t)b*T_*KCOLS_ + (size_t)kvh*HD_;

    // ---- load Q tile (64x128) -> Qs as tf32 ----
#pragma unroll
    for (int it = 0; it < 16; it++) {
        int i = it * 128 + tid;
        int r = i >> 5;
        int c4 = (i & 31) << 2;
        float4 v = *(const float4*)(qp + (size_t)(qBase + r) * QCOLS_ + c4);
        unsigned* dst = Qs + r * AT_LDK + c4;
        dst[0] = f2tf32(v.x); dst[1] = f2tf32(v.y);
        dst[2] = f2tf32(v.z); dst[3] = f2tf32(v.w);
    }

    float m0 = -INFINITY, m1 = -INFINITY, l0 = 0.f, l1 = 0.f;
    float o[16][4];
#pragma unroll
    for (int nf = 0; nf < 16; nf++)
#pragma unroll
        for (int q = 0; q < 4; q++) o[nf][q] = 0.f;

    const int r0g = qBase + 16 * warp + gid;
    const int r1g = r0g + 8;

    for (int jt = 0; jt <= qt; jt++) {
        const int kBase = jt * 64;

#pragma unroll
        for (int it = 0; it < 16; it++) {
            int i = it * 128 + tid;
            int r = i >> 5;
            int c4 = (i & 31) << 2;
            const float4 kv = *(const float4*)(kp + (size_t)(kBase + r) * KCOLS_ + c4);
            unsigned* kd = Ks + r * AT_LDK + c4;
            kd[0] = f2tf32(kv.x); kd[1] = f2tf32(kv.y);
            kd[2] = f2tf32(kv.z); kd[3] = f2tf32(kv.w);
            const float4 vv = *(const float4*)(vp + (size_t)(kBase + r) * KCOLS_ + c4);
            uint4 vt;
            vt.x = f2tf32(vv.x); vt.y = f2tf32(vv.y);
            vt.z = f2tf32(vv.z); vt.w = f2tf32(vv.w);
            *(uint4*)(Vt + (c4 >> 2) * AT_VROW + r * 4) = vt;
        }
        __syncthreads();

        // ---- S = Q . K^T ----
        float s[8][4];
#pragma unroll
        for (int nf = 0; nf < 8; nf++)
#pragma unroll
            for (int q = 0; q < 4; q++) s[nf][q] = 0.f;

#pragma unroll
        for (int kc = 0; kc < 16; kc++) {
            const int k = kc * 8 + m4;
            const int r = 16 * warp + gid;
            unsigned a[4];
            a[0] = Qs[r       * AT_LDK + k];
            a[1] = Qs[(r + 8) * AT_LDK + k];
            a[2] = Qs[r       * AT_LDK + k + 4];
            a[3] = Qs[(r + 8) * AT_LDK + k + 4];
#pragma unroll
            for (int nf = 0; nf < 8; nf++) {
                const int n = nf * 8 + gid;
                unsigned bq[2];
                bq[0] = Ks[n * AT_LDK + k];
                bq[1] = Ks[n * AT_LDK + k + 4];
                mma_tf32(s[nf], a, bq);
            }
        }

        // ---- softcap + causal mask ----
        const int cb = kBase + 2 * m4;
#pragma unroll
        for (int nf = 0; nf < 8; nf++) {
#pragma unroll
            for (int q = 0; q < 4; q++) {
                int col = cb + 8 * nf + (q & 1);
                int row = (q < 2) ? r0g : r1g;
                float val = CAP_ * tanh_fast(s[nf][q] * (1.0f / CAP_));
                s[nf][q] = (col > row) ? -INFINITY : val;
            }
        }

        // ---- online softmax ----
        float rmax0 = -INFINITY, rmax1 = -INFINITY;
#pragma unroll
        for (int nf = 0; nf < 8; nf++) {
            rmax0 = fmaxf(rmax0, fmaxf(s[nf][0], s[nf][1]));
            rmax1 = fmaxf(rmax1, fmaxf(s[nf][2], s[nf][3]));
        }
#pragma unroll
        for (int off = 1; off <= 2; off <<= 1) {
            rmax0 = fmaxf(rmax0, __shfl_xor_sync(0xffffffffu, rmax0, off));
            rmax1 = fmaxf(rmax1, __shfl_xor_sync(0xffffffffu, rmax1, off));
        }
        float mn0 = fmaxf(m0, rmax0), mn1 = fmaxf(m1, rmax1);
        float al0 = __expf(m0 - mn0), al1 = __expf(m1 - mn1);
        m0 = mn0; m1 = mn1;

        float rs0 = 0.f, rs1 = 0.f;
#pragma unroll
        for (int nf = 0; nf < 8; nf++) {
            float p0 = __expf(s[nf][0] - mn0);
            float p1 = __expf(s[nf][1] - mn0);
            float p2 = __expf(s[nf][2] - mn1);
            float p3 = __expf(s[nf][3] - mn1);
            rs0 += p0 + p1; rs1 += p2 + p3;
            s[nf][0] = p0; s[nf][1] = p1; s[nf][2] = p2; s[nf][3] = p3;
        }
#pragma unroll
        for (int off = 1; off <= 2; off <<= 1) {
            rs0 += __shfl_xor_sync(0xffffffffu, rs0, off);
            rs1 += __shfl_xor_sync(0xffffffffu, rs1, off);
        }
        l0 = l0 * al0 + rs0;
        l1 = l1 * al1 + rs1;
#pragma unroll
        for (int nf = 0; nf < 16; nf++) {
            o[nf][0] *= al0; o[nf][1] *= al0;
            o[nf][2] *= al1; o[nf][3] *= al1;
        }

        // ---- O += P . V (kappa-permuted V) ----
        const int vlow = (lane >> 4) * AT_VROW + ((lane >> 2) & 3) + 8 * m4;
#pragma unroll
        for (int kc = 0; kc < 8; kc++) {
            unsigned pa[4];
            pa[0] = f2tf32(s[kc][0]);
            pa[1] = f2tf32(s[kc][2]);
            pa[2] = f2tf32(s[kc][1]);
            pa[3] = f2tf32(s[kc][3]);
#pragma unroll
            for (int nf = 0; nf < 16; nf++) {
                const unsigned* vb = Vt + 2 * nf * AT_VROW + 32 * kc + vlow;
                unsigned bv[2];
                bv[0] = vb[0];
                bv[1] = vb[4];
                mma_tf32(o[nf], pa, bv);
            }
        }
        __syncthreads();
    }

    // ---- epilogue: /l, store as tf32 bits ----
    float inv0 = 1.0f / l0, inv1 = 1.0f / l1;
    unsigned* op0 = O + ((size_t)b*T_ + r0g) * QCOLS_ + (size_t)h*HD_;
    unsigned* op1 = O + ((size_t)b*T_ + r1g) * QCOLS_ + (size_t)h*HD_;
#pragma unroll
    for (int nf = 0; nf < 16; nf++) {
        int col = 8 * nf + 2 * m4;
        uint2 u0, u1;
        u0.x = f2tf32(o[nf][0] * inv0); u0.y = f2tf32(o[nf][1] * inv0);
        u1.x = f2tf32(o[nf][2] * inv1); u1.y = f2tf32(o[nf][3] * inv1);
        *(uint2*)(op0 + col) = u0;
        *(uint2*)(op1 + col) = u1;
    }
}

// ============================================================================
// launch
// ============================================================================
extern "C" void kernel_launch(void* const* d_in, const int* in_sizes, int n_in,
                              void* d_out, int out_size)
{
    const float* x  = (const float*)d_in[0];
    const float* wq = (const float*)d_in[1];
    const float* wk = (const float*)d_in[2];
    const float* wv = (const float*)d_in[3];
    const float* wo = (const float*)d_in[4];
    const float* qg = (const float*)d_in[5];
    const float* kg = (const float*)d_in[6];
    float* out = (float*)d_out;

    float *q, *k, *v;
    unsigned *ot, *xt, *wqt, *wkt, *wvt, *wot;
    cudaGetSymbolAddress((void**)&q,  g_q);
    cudaGetSymbolAddress((void**)&k,  g_k);
    cudaGetSymbolAddress((void**)&v,  g_v);
    cudaGetSymbolAddress((void**)&ot, g_ot);
    cudaGetSymbolAddress((void**)&xt, g_xt);
    cudaGetSymbolAddress((void**)&wqt, g_wqt);
    cudaGetSymbolAddress((void**)&wkt, g_wkt);
    cudaGetSymbolAddress((void**)&wvt, g_wvt);
    cudaGetSymbolAddress((void**)&wot, g_wot);

    static bool attr_set = false;
    if (!attr_set) {
        cudaFuncSetAttribute(gemm_tf32, cudaFuncAttributeMaxDynamicSharedMemorySize, GEMM_SMEM);
        cudaFuncSetAttribute(attn_mma, cudaFuncAttributeMaxDynamicSharedMemorySize, ATTN_SMEM);
        attr_set = true;
    }

    // pre-convert all GEMM operands to tf32 bits (one-shot elementwise passes)
    cvt_tf32_k<<<(BT_*D_/4 + 255)/256, 256>>>(x,  xt,  BT_*D_/4);
    cvt_tf32_k<<<(QCOLS_*D_/4 + 255)/256, 256>>>(wq, wqt, QCOLS_*D_/4);
    cvt_tf32_k<<<(KCOLS_*D_/4 + 255)/256, 256>>>(wk, wkt, KCOLS_*D_/4);
    cvt_tf32_k<<<(KCOLS_*D_/4 + 255)/256, 256>>>(wv, wvt, KCOLS_*D_/4);
    cvt_tf32_k<<<(D_*QCOLS_/4 + 255)/256, 256>>>(wo, wot, D_*QCOLS_/4);

    // projections (tf32 tensor cores, cvt-free inner loop)
    gemm_tf32<<<dim3(QCOLS_/128, BT_/128), 256, GEMM_SMEM>>>(xt, wqt, q, BT_, QCOLS_, D_);
    gemm_tf32<<<dim3(KCOLS_/128, BT_/128), 256, GEMM_SMEM>>>(xt, wkt, k, BT_, KCOLS_, D_);
    gemm_tf32<<<dim3(KCOLS_/128, BT_/128), 256, GEMM_SMEM>>>(xt, wvt, v, BT_, KCOLS_, D_);

    // QK-norm (fold attention scale into q)
    rmsnorm_k<<<(BT_*H_)/8, 256>>>(q, qg, BT_*H_, SCALE_);
    rmsnorm_k<<<(BT_*KVH_)/8, 256>>>(k, kg, BT_*KVH_, 1.0f);

    // attention (tf32 tensor cores; writes tf32 bits for the O-projection)
    attn_mma<<<dim3(T_/64, B_*H_), 128, ATTN_SMEM>>>(q, k, v, ot);

    // output projection
    gemm_tf32<<<dim3(D_/128, BT_/128), 256, GEMM_SMEM>>>(ot, wot, out, BT_, D_, D_);
}

// round 9
// speedup vs baseline: 1.5058x; 1.5058x over previous
#include <cuda_runtime.h>
#include <math.h>

// ---- problem constants ----
#define D_   2048
#define H_   16
#define KVH_ 4
#define HD_  128
#define B_   2
#define T_   2048
#define BT_  (B_*T_)          // 4096
#define QCOLS_ (H_*HD_)       // 2048
#define KCOLS_ (KVH_*HD_)     // 512
#define CAP_ 50.0f
#define SCALE_ 0.08838834764831845f  // 128^-0.5

// ---- scratch (static device arrays; no allocations allowed) ----
static __device__ float g_q[BT_*QCOLS_];
static __device__ float g_k[BT_*KCOLS_];
static __device__ float g_v[BT_*KCOLS_];
static __device__ float g_o[BT_*QCOLS_];

// ============================================================================
// tf32 mma helpers
// ============================================================================
__device__ __forceinline__ unsigned f2tf32(float x) {
    unsigned u;
    asm("cvt.rna.tf32.f32 %0, %1;" : "=r"(u) : "f"(x));
    return u;
}

__device__ __forceinline__ void mma_tf32(float* c, const unsigned* a, const unsigned* b) {
    asm volatile(
        "mma.sync.aligned.m16n8k8.row.col.f32.tf32.tf32.f32 "
        "{%0,%1,%2,%3}, {%4,%5,%6,%7}, {%8,%9}, {%0,%1,%2,%3};"
        : "+f"(c[0]), "+f"(c[1]), "+f"(c[2]), "+f"(c[3])
        : "r"(a[0]), "r"(a[1]), "r"(a[2]), "r"(a[3]), "r"(b[0]), "r"(b[1]));
}

__device__ __forceinline__ float tanh_fast(float x) {
    float r;
    asm("tanh.approx.f32 %0, %1;" : "=f"(r) : "f"(x));
    return r;
}

__device__ __forceinline__ void cp_async16(void* smem_dst, const void* gsrc) {
    unsigned saddr = (unsigned)__cvta_generic_to_shared(smem_dst);
    asm volatile("cp.async.cg.shared.global [%0], [%1], 16;" :: "r"(saddr), "l"(gsrc));
}
#define CP_COMMIT() asm volatile("cp.async.commit_group;")
#define CP_WAIT0()  asm volatile("cp.async.wait_group 0;")

// ============================================================================
// tf32 tensor-core GEMM (R5-proven): C[M,N] = A[M,K] * B[N,K]^T.
// 128x128x32 tiles, 256 thr, 8 warps (4x2), warp 32x64, 2-stage cp.async,
// pad-36 rows, cvt at use (overlaps on F2FP pipe; tensor pipe is the limit).
// ============================================================================
#define BK_ 32
#define LDP_ 36
#define GEMM_SMEM (4 * 128 * LDP_ * (int)sizeof(float))  // 2 stages x (A+B)

__global__ __launch_bounds__(256) void gemm_tf32(
    const float* __restrict__ A, const float* __restrict__ Bw,
    float* __restrict__ C, int M, int N, int K)
{
    extern __shared__ float sm[];
    float* AsBase = sm;                    // [2][128*LDP_]
    float* BsBase = sm + 2 * 128 * LDP_;   // [2][128*LDP_]

    const int tid  = threadIdx.x;
    const int lane = tid & 31;
    const int warp = tid >> 5;
    const int wm = (warp & 3) * 32;
    const int wn = (warp >> 2) * 64;
    const int rowBase = blockIdx.y * 128;
    const int colBase = blockIdx.x * 128;

    const int lr = tid >> 3;
    const int lc = (tid & 7) * 4;

    float acc[2][8][4];
#pragma unroll
    for (int mi = 0; mi < 2; mi++)
#pragma unroll
        for (int ni = 0; ni < 8; ni++)
#pragma unroll
            for (int q = 0; q < 4; q++) acc[mi][ni][q] = 0.f;

    const int ntiles = K / BK_;

    {
        float* as = AsBase;
        float* bs = BsBase;
#pragma unroll
        for (int it = 0; it < 4; it++) {
            int r = it * 32 + lr;
            cp_async16(as + r * LDP_ + lc, A  + (size_t)(rowBase + r) * K + lc);
            cp_async16(bs + r * LDP_ + lc, Bw + (size_t)(colBase + r) * K + lc);
        }
        CP_COMMIT();
    }

    int cur = 0;
    for (int t = 0; t < ntiles; t++) {
        CP_WAIT0();
        __syncthreads();

        if (t + 1 < ntiles) {
            int k0 = (t + 1) * BK_;
            float* as = AsBase + (cur ^ 1) * 128 * LDP_;
            float* bs = BsBase + (cur ^ 1) * 128 * LDP_;
#pragma unroll
            for (int it = 0; it < 4; it++) {
                int r = it * 32 + lr;
                cp_async16(as + r * LDP_ + lc, A  + (size_t)(rowBase + r) * K + k0 + lc);
                cp_async16(bs + r * LDP_ + lc, Bw + (size_t)(colBase + r) * K + k0 + lc);
            }
            CP_COMMIT();
        }

        const float* as = AsBase + cur * 128 * LDP_;
        const float* bs = BsBase + cur * 128 * LDP_;
#pragma unroll
        for (int kk = 0; kk < 4; kk++) {
            const int k = kk * 8 + (lane & 3);
            unsigned af[2][4], bf[8][2];
#pragma unroll
            for (int mi = 0; mi < 2; mi++) {
                int r = wm + mi * 16 + (lane >> 2);
                af[mi][0] = f2tf32(as[r       * LDP_ + k]);
                af[mi][1] = f2tf32(as[(r + 8) * LDP_ + k]);
                af[mi][2] = f2tf32(as[r       * LDP_ + k + 4]);
                af[mi][3] = f2tf32(as[(r + 8) * LDP_ + k + 4]);
            }
#pragma unroll
            for (int ni = 0; ni < 8; ni++) {
                int n = wn + ni * 8 + (lane >> 2);
                bf[ni][0] = f2tf32(bs[n * LDP_ + k]);
                bf[ni][1] = f2tf32(bs[n * LDP_ + k + 4]);
            }
#pragma unroll
            for (int mi = 0; mi < 2; mi++)
#pragma unroll
                for (int ni = 0; ni < 8; ni++)
                    mma_tf32(acc[mi][ni], af[mi], bf[ni]);
        }
        cur ^= 1;
    }

#pragma unroll
    for (int mi = 0; mi < 2; mi++) {
        int r0 = rowBase + wm + mi * 16 + (lane >> 2);
#pragma unroll
        for (int ni = 0; ni < 8; ni++) {
            int c0 = colBase + wn + ni * 8 + (lane & 3) * 2;
            *(float2*)&C[(size_t)r0       * N + c0] = make_float2(acc[mi][ni][0], acc[mi][ni][1]);
            *(float2*)&C[(size_t)(r0 + 8) * N + c0] = make_float2(acc[mi][ni][2], acc[mi][ni][3]);
        }
    }
}

// ============================================================================
// RMSNorm: one warp per 128-element row, in place.
// ============================================================================
__global__ __launch_bounds__(256) void rmsnorm_k(
    float* __restrict__ data, const float* __restrict__ gamma,
    int nrows, float scale)
{
    int row  = blockIdx.x * 8 + (threadIdx.x >> 5);
    int lane = threadIdx.x & 31;
    if (row >= nrows) return;
    float4 v = ((float4*)data)[(size_t)row * 32 + lane];
    float ss = v.x*v.x + v.y*v.y + v.z*v.z + v.w*v.w;
#pragma unroll
    for (int off = 16; off > 0; off >>= 1)
        ss += __shfl_xor_sync(0xffffffffu, ss, off);
    float r = rsqrtf(ss * (1.0f/128.0f) + 1e-6f) * scale;
    float4 g = ((const float4*)gamma)[lane];
    v.x *= r * g.x; v.y *= r * g.y; v.z *= r * g.z; v.w *= r * g.w;
    ((float4*)data)[(size_t)row * 32 + lane] = v;
}

// ============================================================================
// Tensor-core flash attention (R5 structure + LSU cuts).
// CTA: 128 threads (4 warps). Tile: 64 q-rows x 64 k-cols, HD=128.
// Changes vs R5: (1) Q fragments register-resident (read once per CTA);
// (2) Ks pair-permuted (p(k)=8(k>>3)+2(k&3)+((k>>2)&1), stride 136) so each
// QK B-fragment is one conflict-free LDS.64. PV path identical to R5.
// ============================================================================
#define AT_LDQ 132
#define AT_LDK 136
#define AT_VROW 260
#define ATTN_SMEM ((64*AT_LDQ + 64*AT_LDK + 32*AT_VROW) * (int)sizeof(unsigned))

__global__ __launch_bounds__(128) void attn_mma(
    const float* __restrict__ Q, const float* __restrict__ Kk,
    const float* __restrict__ Vv, float* __restrict__ O)
{
    extern __shared__ unsigned smu[];
    unsigned* Qs = smu;
    unsigned* Ks = Qs + 64 * AT_LDQ;
    unsigned* Vt = Ks + 64 * AT_LDK;

    const int tid  = threadIdx.x;
    const int lane = tid & 31;
    const int warp = tid >> 5;
    const int gid  = lane >> 2;      // group id (row within frag)
    const int m4   = lane & 3;       // thread-in-group

    const int bh = blockIdx.y;
    const int b = bh >> 4, h = bh & 15, kvh = h >> 2;
    const int qt = gridDim.x - 1 - blockIdx.x;     // heavy tiles first
    const int qBase = qt * 64;

    const float* qp = Q  + (size_t)b*T_*QCOLS_ + (size_t)h*HD_;
    const float* kp = Kk + (size_t)b*T_*KCOLS_ + (size_t)kvh*HD_;
    const float* vp = Vv + (size_t)b*T_*KCOLS_ + (size_t)kvh*HD_;

    // ---- load Q tile (64x128) -> Qs as tf32 (unpermuted) ----
#pragma unroll
    for (int it = 0; it < 16; it++) {
        int i = it * 128 + tid;
        int r = i >> 5;
        int c4 = (i & 31) << 2;
        float4 v = *(const float4*)(qp + (size_t)(qBase + r) * QCOLS_ + c4);
        unsigned* dst = Qs + r * AT_LDQ + c4;
        dst[0] = f2tf32(v.x); dst[1] = f2tf32(v.y);
        dst[2] = f2tf32(v.z); dst[3] = f2tf32(v.w);
    }
    __syncthreads();

    // ---- hoist Q fragments to registers (once per CTA) ----
    unsigned qa[16][4];
    {
        const int r = 16 * warp + gid;
#pragma unroll
        for (int kc = 0; kc < 16; kc++) {
            const int k = kc * 8 + m4;
            qa[kc][0] = Qs[r       * AT_LDQ + k];
            qa[kc][1] = Qs[(r + 8) * AT_LDQ + k];
            qa[kc][2] = Qs[r       * AT_LDQ + k + 4];
            qa[kc][3] = Qs[(r + 8) * AT_LDQ + k + 4];
        }
    }

    float m0 = -INFINITY, m1 = -INFINITY, l0 = 0.f, l1 = 0.f;
    float o[16][4];
#pragma unroll
    for (int nf = 0; nf < 16; nf++)
#pragma unroll
        for (int q = 0; q < 4; q++) o[nf][q] = 0.f;

    const int r0g = qBase + 16 * warp + gid;
    const int r1g = r0g + 8;

    for (int jt = 0; jt <= qt; jt++) {
        const int kBase = jt * 64;

        // ---- load K -> Ks (pair-permuted) and V -> Vt (R5 layout) ----
#pragma unroll
        for (int it = 0; it < 16; it++) {
            int i = it * 128 + tid;
            int r = i >> 5;
            int ln = i & 31;
            int c4 = ln << 2;
            const float4 kv = *(const float4*)(kp + (size_t)(kBase + r) * KCOLS_ + c4);
            unsigned* kd = Ks + r * AT_LDK + 8 * (ln >> 1) + (ln & 1);
            kd[0] = f2tf32(kv.x); kd[2] = f2tf32(kv.y);
            kd[4] = f2tf32(kv.z); kd[6] = f2tf32(kv.w);
            const float4 vv = *(const float4*)(vp + (size_t)(kBase + r) * KCOLS_ + c4);
            uint4 vt;
            vt.x = f2tf32(vv.x); vt.y = f2tf32(vv.y);
            vt.z = f2tf32(vv.z); vt.w = f2tf32(vv.w);
            *(uint4*)(Vt + ln * AT_VROW + r * 4) = vt;
        }
        __syncthreads();

        // ---- S = Q . K^T (Q from regs, K frag = one LDS.64) ----
        float s[8][4];
#pragma unroll
        for (int nf = 0; nf < 8; nf++)
#pragma unroll
            for (int q = 0; q < 4; q++) s[nf][q] = 0.f;

#pragma unroll
        for (int kc = 0; kc < 16; kc++) {
#pragma unroll
            for (int nf = 0; nf < 8; nf++) {
                const int n = nf * 8 + gid;
                uint2 bb = *(const uint2*)(Ks + n * AT_LDK + 8 * kc + 2 * m4);
                unsigned bq[2] = { bb.x, bb.y };
                mma_tf32(s[nf], qa[kc], bq);
            }
        }

        // ---- softcap + causal mask ----
        const int cb = kBase + 2 * m4;
#pragma unroll
        for (int nf = 0; nf < 8; nf++) {
#pragma unroll
            for (int q = 0; q < 4; q++) {
                int col = cb + 8 * nf + (q & 1);
                int row = (q < 2) ? r0g : r1g;
                float val = CAP_ * tanh_fast(s[nf][q] * (1.0f / CAP_));
                s[nf][q] = (col > row) ? -INFINITY : val;
            }
        }

        // ---- online softmax ----
        float rmax0 = -INFINITY, rmax1 = -INFINITY;
#pragma unroll
        for (int nf = 0; nf < 8; nf++) {
            rmax0 = fmaxf(rmax0, fmaxf(s[nf][0], s[nf][1]));
            rmax1 = fmaxf(rmax1, fmaxf(s[nf][2], s[nf][3]));
        }
#pragma unroll
        for (int off = 1; off <= 2; off <<= 1) {
            rmax0 = fmaxf(rmax0, __shfl_xor_sync(0xffffffffu, rmax0, off));
            rmax1 = fmaxf(rmax1, __shfl_xor_sync(0xffffffffu, rmax1, off));
        }
        float mn0 = fmaxf(m0, rmax0), mn1 = fmaxf(m1, rmax1);
        float al0 = __expf(m0 - mn0), al1 = __expf(m1 - mn1);
        m0 = mn0; m1 = mn1;

        float rs0 = 0.f, rs1 = 0.f;
#pragma unroll
        for (int nf = 0; nf < 8; nf++) {
            float p0 = __expf(s[nf][0] - mn0);
            float p1 = __expf(s[nf][1] - mn0);
            float p2 = __expf(s[nf][2] - mn1);
            float p3 = __expf(s[nf][3] - mn1);
            rs0 += p0 + p1; rs1 += p2 + p3;
            s[nf][0] = p0; s[nf][1] = p1; s[nf][2] = p2; s[nf][3] = p3;
        }
#pragma unroll
        for (int off = 1; off <= 2; off <<= 1) {
            rs0 += __shfl_xor_sync(0xffffffffu, rs0, off);
            rs1 += __shfl_xor_sync(0xffffffffu, rs1, off);
        }
        l0 = l0 * al0 + rs0;
        l1 = l1 * al1 + rs1;
#pragma unroll
        for (int nf = 0; nf < 16; nf++) {
            o[nf][0] *= al0; o[nf][1] *= al0;
            o[nf][2] *= al1; o[nf][3] *= al1;
        }

        // ---- O += P . V (kappa-permuted V, R5 path) ----
        const int vlow = (lane >> 4) * AT_VROW + ((lane >> 2) & 3) + 8 * m4;
#pragma unroll
        for (int kc = 0; kc < 8; kc++) {
            unsigned pa[4];
            pa[0] = f2tf32(s[kc][0]);
            pa[1] = f2tf32(s[kc][2]);
            pa[2] = f2tf32(s[kc][1]);
            pa[3] = f2tf32(s[kc][3]);
#pragma unroll
            for (int nf = 0; nf < 16; nf++) {
                const unsigned* vb = Vt + 2 * nf * AT_VROW + 32 * kc + vlow;
                unsigned bv[2];
                bv[0] = vb[0];
                bv[1] = vb[4];
                mma_tf32(o[nf], pa, bv);
            }
        }
        __syncthreads();
    }

    // ---- epilogue: /l, store ----
    float inv0 = 1.0f / l0, inv1 = 1.0f / l1;
    float* op0 = O + ((size_t)b*T_ + r0g) * QCOLS_ + (size_t)h*HD_;
    float* op1 = O + ((size_t)b*T_ + r1g) * QCOLS_ + (size_t)h*HD_;
#pragma unroll
    for (int nf = 0; nf < 16; nf++) {
        int col = 8 * nf + 2 * m4;
        *(float2*)(op0 + col) = make_float2(o[nf][0] * inv0, o[nf][1] * inv0);
        *(float2*)(op1 + col) = make_float2(o[nf][2] * inv1, o[nf][3] * inv1);
    }
}

// ============================================================================
// launch
// ============================================================================
extern "C" void kernel_launch(void* const* d_in, const int* in_sizes, int n_in,
                              void* d_out, int out_size)
{
    const float* x  = (const float*)d_in[0];
    const float* wq = (const float*)d_in[1];
    const float* wk = (const float*)d_in[2];
    const float* wv = (const float*)d_in[3];
    const float* wo = (const float*)d_in[4];
    const float* qg = (const float*)d_in[5];
    const float* kg = (const float*)d_in[6];
    float* out = (float*)d_out;

    float *q, *k, *v, *o;
    cudaGetSymbolAddress((void**)&q, g_q);
    cudaGetSymbolAddress((void**)&k, g_k);
    cudaGetSymbolAddress((void**)&v, g_v);
    cudaGetSymbolAddress((void**)&o, g_o);

    static bool attr_set = false;
    if (!attr_set) {
        cudaFuncSetAttribute(gemm_tf32, cudaFuncAttributeMaxDynamicSharedMemorySize, GEMM_SMEM);
        cudaFuncSetAttribute(attn_mma, cudaFuncAttributeMaxDynamicSharedMemorySize, ATTN_SMEM);
        attr_set = true;
    }

    // projections (tf32 tensor cores)
    gemm_tf32<<<dim3(QCOLS_/128, BT_/128), 256, GEMM_SMEM>>>(x, wq, q, BT_, QCOLS_, D_);
    gemm_tf32<<<dim3(KCOLS_/128, BT_/128), 256, GEMM_SMEM>>>(x, wk, k, BT_, KCOLS_, D_);
    gemm_tf32<<<dim3(KCOLS_/128, BT_/128), 256, GEMM_SMEM>>>(x, wv, v, BT_, KCOLS_, D_);

    // QK-norm (fold attention scale into q)
    rmsnorm_k<<<(BT_*H_)/8, 256>>>(q, qg, BT_*H_, SCALE_);
    rmsnorm_k<<<(BT_*KVH_)/8, 256>>>(k, kg, BT_*KVH_, 1.0f);

    // attention (tf32 tensor cores)
    attn_mma<<<dim3(T_/64, B_*H_), 128, ATTN_SMEM>>>(q, k, v, o);

    // output projection
    gemm_tf32<<<dim3(D_/128, BT_/128), 256, GEMM_SMEM>>>(o, wo, out, BT_, D_, D_);
}

// round 12
// speedup vs baseline: 1.8671x; 1.2400x over previous
#include <cuda_runtime.h>
#include <math.h>
#include <stdint.h>

// ---- problem constants ----
#define D_   2048
#define H_   16
#define KVH_ 4
#define HD_  128
#define B_   2
#define T_   2048
#define BT_  (B_*T_)          // 4096
#define QCOLS_ (H_*HD_)       // 2048
#define KCOLS_ (KVH_*HD_)     // 512
#define CAP_ 50.0f
#define SCALE_ 0.08838834764831845f  // 128^-0.5

// ---- scratch (static device arrays; no allocations allowed) ----
static __device__ float g_q[BT_*QCOLS_];
static __device__ float g_k[BT_*KCOLS_];
static __device__ float g_v[BT_*KCOLS_];
static __device__ float g_o[BT_*QCOLS_];

// ============================================================================
// fp16 mma helpers
// ============================================================================
__device__ __forceinline__ unsigned pack_h2(float lo, float hi) {
    unsigned u;
    asm("cvt.rn.f16x2.f32 %0, %1, %2;" : "=r"(u) : "f"(hi), "f"(lo));
    return u;
}

__device__ __forceinline__ void mma_f16(float* c, const unsigned* a, const unsigned* b) {
    asm volatile(
        "mma.sync.aligned.m16n8k16.row.col.f32.f16.f16.f32 "
        "{%0,%1,%2,%3}, {%4,%5,%6,%7}, {%8,%9}, {%0,%1,%2,%3};"
        : "+f"(c[0]), "+f"(c[1]), "+f"(c[2]), "+f"(c[3])
        : "r"(a[0]), "r"(a[1]), "r"(a[2]), "r"(a[3]), "r"(b[0]), "r"(b[1]));
}

__device__ __forceinline__ void ldsm4(unsigned& r0, unsigned& r1, unsigned& r2, unsigned& r3,
                                      unsigned addr) {
    asm volatile("ldmatrix.sync.aligned.m8n8.x4.shared.b16 {%0,%1,%2,%3}, [%4];"
        : "=r"(r0), "=r"(r1), "=r"(r2), "=r"(r3) : "r"(addr));
}

__device__ __forceinline__ void ldsm4t(unsigned& r0, unsigned& r1, unsigned& r2, unsigned& r3,
                                       unsigned addr) {
    asm volatile("ldmatrix.sync.aligned.m8n8.x4.trans.shared.b16 {%0,%1,%2,%3}, [%4];"
        : "=r"(r0), "=r"(r1), "=r"(r2), "=r"(r3) : "r"(addr));
}

__device__ __forceinline__ float tanh_fast(float x) {
    float r;
    asm("tanh.approx.f32 %0, %1;" : "=f"(r) : "f"(x));
    return r;
}

__device__ __forceinline__ void cp_async16(void* smem_dst, const void* gsrc) {
    unsigned saddr = (unsigned)__cvta_generic_to_shared(smem_dst);
    asm volatile("cp.async.cg.shared.global [%0], [%1], 16;" :: "r"(saddr), "l"(gsrc));
}
#define CP_COMMIT() asm volatile("cp.async.commit_group;")
#define CP_WAIT0()  asm volatile("cp.async.wait_group 0;")

// ============================================================================
// fp16 tensor-core GEMM: C[M,N] = A[M,K]*B[N,K]^T (f32 in global/smem).
// R9 structure: 128x128x32 tiles, 256 thr, 8 warps (4x2), warp 32x64,
// 2-stage cp.async pipeline, pad-36 f32 rows. Fragments: LDS.64 f32 pair +
// cvt.rn.f16x2 pack; mma.m16n8k16 (2x MACs per instruction vs tf32 k8).
// ============================================================================
#define BK_ 32
#define LDP_ 36
#define GEMM_SMEM (4 * 128 * LDP_ * (int)sizeof(float))  // 2 stages x (A+B)

__global__ __launch_bounds__(256) void gemm_f16(
    const float* __restrict__ A, const float* __restrict__ Bw,
    float* __restrict__ C, int M, int N, int K)
{
    extern __shared__ float sm[];
    float* AsBase = sm;
    float* BsBase = sm + 2 * 128 * LDP_;

    const int tid  = threadIdx.x;
    const int lane = tid & 31;
    const int warp = tid >> 5;
    const int gid  = lane >> 2, m4 = lane & 3;
    const int wm = (warp & 3) * 32;
    const int wn = (warp >> 2) * 64;
    const int rowBase = blockIdx.y * 128;
    const int colBase = blockIdx.x * 128;

    const int lr = tid >> 3;
    const int lc = (tid & 7) * 4;

    float acc[2][8][4];
#pragma unroll
    for (int mi = 0; mi < 2; mi++)
#pragma unroll
        for (int ni = 0; ni < 8; ni++)
#pragma unroll
            for (int q = 0; q < 4; q++) acc[mi][ni][q] = 0.f;

    const int ntiles = K / BK_;

    {
        float* as = AsBase;
        float* bs = BsBase;
#pragma unroll
        for (int it = 0; it < 4; it++) {
            int r = it * 32 + lr;
            cp_async16(as + r * LDP_ + lc, A  + (size_t)(rowBase + r) * K + lc);
            cp_async16(bs + r * LDP_ + lc, Bw + (size_t)(colBase + r) * K + lc);
        }
        CP_COMMIT();
    }

    int cur = 0;
    for (int t = 0; t < ntiles; t++) {
        CP_WAIT0();
        __syncthreads();

        if (t + 1 < ntiles) {
            int k0 = (t + 1) * BK_;
            float* as = AsBase + (cur ^ 1) * 128 * LDP_;
            float* bs = BsBase + (cur ^ 1) * 128 * LDP_;
#pragma unroll
            for (int it = 0; it < 4; it++) {
                int r = it * 32 + lr;
                cp_async16(as + r * LDP_ + lc, A  + (size_t)(rowBase + r) * K + k0 + lc);
                cp_async16(bs + r * LDP_ + lc, Bw + (size_t)(colBase + r) * K + k0 + lc);
            }
            CP_COMMIT();
        }

        const float* as = AsBase + cur * 128 * LDP_;
        const float* bs = BsBase + cur * 128 * LDP_;
#pragma unroll
        for (int kc = 0; kc < 2; kc++) {
            const int kb = kc * 16 + 2 * m4;   // f32 column of the k-pair
            unsigned af[2][4], bf[8][2];
#pragma unroll
            for (int mi = 0; mi < 2; mi++) {
                int r = wm + 16 * mi + gid;
                float2 p0 = *(const float2*)(as + r       * LDP_ + kb);
                float2 p1 = *(const float2*)(as + (r + 8) * LDP_ + kb);
                float2 p2 = *(const float2*)(as + r       * LDP_ + kb + 8);
                float2 p3 = *(const float2*)(as + (r + 8) * LDP_ + kb + 8);
                af[mi][0] = pack_h2(p0.x, p0.y);
                af[mi][1] = pack_h2(p1.x, p1.y);
                af[mi][2] = pack_h2(p2.x, p2.y);
                af[mi][3] = pack_h2(p3.x, p3.y);
            }
#pragma unroll
            for (int ni = 0; ni < 8; ni++) {
                int n = wn + 8 * ni + gid;
                float2 q0 = *(const float2*)(bs + n * LDP_ + kb);
                float2 q1 = *(const float2*)(bs + n * LDP_ + kb + 8);
                bf[ni][0] = pack_h2(q0.x, q0.y);
                bf[ni][1] = pack_h2(q1.x, q1.y);
            }
#pragma unroll
            for (int mi = 0; mi < 2; mi++)
#pragma unroll
                for (int ni = 0; ni < 8; ni++)
                    mma_f16(acc[mi][ni], af[mi], bf[ni]);
        }
        cur ^= 1;
    }

#pragma unroll
    for (int mi = 0; mi < 2; mi++) {
        int r0 = rowBase + wm + 16 * mi + gid;
#pragma unroll
        for (int ni = 0; ni < 8; ni++) {
            int c0 = colBase + wn + ni * 8 + m4 * 2;
            *(float2*)&C[(size_t)r0       * N + c0] = make_float2(acc[mi][ni][0], acc[mi][ni][1]);
            *(float2*)&C[(size_t)(r0 + 8) * N + c0] = make_float2(acc[mi][ni][2], acc[mi][ni][3]);
        }
    }
}

// ============================================================================
// RMSNorm: one warp per 128-element row, in place.
// ============================================================================
__global__ __launch_bounds__(256) void rmsnorm_k(
    float* __restrict__ data, const float* __restrict__ gamma,
    int nrows, float scale)
{
    int row  = blockIdx.x * 8 + (threadIdx.x >> 5);
    int lane = threadIdx.x & 31;
    if (row >= nrows) return;
    float4 v = ((float4*)data)[(size_t)row * 32 + lane];
    float ss = v.x*v.x + v.y*v.y + v.z*v.z + v.w*v.w;
#pragma unroll
    for (int off = 16; off > 0; off >>= 1)
        ss += __shfl_xor_sync(0xffffffffu, ss, off);
    float r = rsqrtf(ss * (1.0f/128.0f) + 1e-6f) * scale;
    float4 g = ((const float4*)gamma)[lane];
    v.x *= r * g.x; v.y *= r * g.y; v.z *= r * g.z; v.w *= r * g.w;
    ((float4*)data)[(size_t)row * 32 + lane] = v;
}

// ============================================================================
// fp16 tensor-core flash attention (causal, tanh softcap).
// CTA: 128 thr (4 warps), tile 64q x 64k, HD=128. smem: half [64][136] for
// Q/K/V (272B rows; ldmatrix phases conflict-free: banks 4g+{0..3}).
// Q A-frags hoisted via ldmatrix.x4 (once); QK B-frags ldmatrix.x4 on K rows;
// PV B-frags ldmatrix.x4.trans on V rows (hw transpose, no scatter stores);
// P packed to half2 A-frags directly from C-frags (no permutation needed).
// ============================================================================
#define AT_LDH 136                       // halfs per row
#define AT_ROWB (AT_LDH*2)               // 272 bytes per row
#define ATTN_SMEM (3 * 64 * AT_ROWB)     // 52224 bytes

__global__ __launch_bounds__(128) void attn_f16(
    const float* __restrict__ Q, const float* __restrict__ Kk,
    const float* __restrict__ Vv, float* __restrict__ O)
{
    extern __shared__ unsigned smw[];    // word view of half smem
    unsigned* Qw = smw;                  // 64*68 words
    unsigned* Kw = Qw + 64 * (AT_LDH/2);
    unsigned* Vw = Kw + 64 * (AT_LDH/2);

    const int tid  = threadIdx.x;
    const int lane = tid & 31;
    const int warp = tid >> 5;
    const int gid  = lane >> 2;
    const int m4   = lane & 3;

    const unsigned qs_b = (unsigned)__cvta_generic_to_shared(Qw);
    const unsigned ks_b = qs_b + 64 * AT_ROWB;
    const unsigned vs_b = ks_b + 64 * AT_ROWB;

    const int bh = blockIdx.y;
    const int b = bh >> 4, h = bh & 15, kvh = h >> 2;
    const int qt = gridDim.x - 1 - blockIdx.x;     // heavy tiles first
    const int qBase = qt * 64;

    const float* qp = Q  + (size_t)b*T_*QCOLS_ + (size_t)h*HD_;
    const float* kp = Kk + (size_t)b*T_*KCOLS_ + (size_t)kvh*HD_;
    const float* vp = Vv + (size_t)b*T_*KCOLS_ + (size_t)kvh*HD_;

    // ---- load Q tile (64x128 f32) -> half smem ----
#pragma unroll
    for (int it = 0; it < 16; it++) {
        int i = it * 128 + tid;
        int r = i >> 5;
        int ln = i & 31;
        float4 v = *(const float4*)(qp + (size_t)(qBase + r) * QCOLS_ + 4 * ln);
        uint2 u;
        u.x = pack_h2(v.x, v.y);
        u.y = pack_h2(v.z, v.w);
        *(uint2*)(Qw + r * (AT_LDH/2) + 2 * ln) = u;
    }
    __syncthreads();

    // ---- hoist Q A-fragments via ldmatrix (once per CTA) ----
    unsigned qa[8][4];
    {
        unsigned qrow = 16 * warp + ((lane >> 3) & 1) * 8 + (lane & 7);
        unsigned qbase = qs_b + qrow * AT_ROWB + (lane >> 4) * 16;
#pragma unroll
        for (int kc = 0; kc < 8; kc++)
            ldsm4(qa[kc][0], qa[kc][1], qa[kc][2], qa[kc][3], qbase + kc * 32);
    }

    // lane-invariant ldmatrix bases for K (non-trans) and V (trans)
    const unsigned kbl = ks_b + ((lane >> 4) * 8 + (lane & 7)) * AT_ROWB + ((lane >> 3) & 1) * 16;
    const unsigned vbl = vs_b + (((lane >> 3) & 1) * 8 + (lane & 7)) * AT_ROWB + (lane >> 4) * 16;

    float m0 = -INFINITY, m1 = -INFINITY, l0 = 0.f, l1 = 0.f;
    float o[16][4];
#pragma unroll
    for (int nf = 0; nf < 16; nf++)
#pragma unroll
        for (int q = 0; q < 4; q++) o[nf][q] = 0.f;

    const int r0g = qBase + 16 * warp + gid;
    const int r1g = r0g + 8;

    for (int jt = 0; jt <= qt; jt++) {
        const int kBase = jt * 64;

        // ---- load K, V tiles (f32 -> half smem, row-major) ----
#pragma unroll
        for (int it = 0; it < 16; it++) {
            int i = it * 128 + tid;
            int r = i >> 5;
            int ln = i & 31;
            float4 kv = *(const float4*)(kp + (size_t)(kBase + r) * KCOLS_ + 4 * ln);
            uint2 uk;
            uk.x = pack_h2(kv.x, kv.y);
            uk.y = pack_h2(kv.z, kv.w);
            *(uint2*)(Kw + r * (AT_LDH/2) + 2 * ln) = uk;
            float4 vv = *(const float4*)(vp + (size_t)(kBase + r) * KCOLS_ + 4 * ln);
            uint2 uv;
            uv.x = pack_h2(vv.x, vv.y);
            uv.y = pack_h2(vv.z, vv.w);
            *(uint2*)(Vw + r * (AT_LDH/2) + 2 * ln) = uv;
        }
        __syncthreads();

        // ---- S = Q . K^T ----
        float s[8][4];
#pragma unroll
        for (int nf = 0; nf < 8; nf++)
#pragma unroll
            for (int q = 0; q < 4; q++) s[nf][q] = 0.f;

#pragma unroll
        for (int kc = 0; kc < 8; kc++) {
#pragma unroll
            for (int nfp = 0; nfp < 4; nfp++) {
                unsigned b0, b1, b2, b3;
                ldsm4(b0, b1, b2, b3, kbl + nfp * (16 * AT_ROWB) + kc * 32);
                unsigned bl[2] = { b0, b1 };
                unsigned bh2[2] = { b2, b3 };
                mma_f16(s[2*nfp],     qa[kc], bl);
                mma_f16(s[2*nfp + 1], qa[kc], bh2);
            }
        }

        // ---- softcap + causal mask (C-frag geometry same as before) ----
        const int cb = kBase + 2 * m4;
#pragma unroll
        for (int nf = 0; nf < 8; nf++) {
#pragma unroll
            for (int q = 0; q < 4; q++) {
                int col = cb + 8 * nf + (q & 1);
                int row = (q < 2) ? r0g : r1g;
                float val = CAP_ * tanh_fast(s[nf][q] * (1.0f / CAP_));
                s[nf][q] = (col > row) ? -INFINITY : val;
            }
        }

        // ---- online softmax ----
        float rmax0 = -INFINITY, rmax1 = -INFINITY;
#pragma unroll
        for (int nf = 0; nf < 8; nf++) {
            rmax0 = fmaxf(rmax0, fmaxf(s[nf][0], s[nf][1]));
            rmax1 = fmaxf(rmax1, fmaxf(s[nf][2], s[nf][3]));
        }
#pragma unroll
        for (int off = 1; off <= 2; off <<= 1) {
            rmax0 = fmaxf(rmax0, __shfl_xor_sync(0xffffffffu, rmax0, off));
            rmax1 = fmaxf(rmax1, __shfl_xor_sync(0xffffffffu, rmax1, off));
        }
        float mn0 = fmaxf(m0, rmax0), mn1 = fmaxf(m1, rmax1);
        float al0 = __expf(m0 - mn0), al1 = __expf(m1 - mn1);
        m0 = mn0; m1 = mn1;

        float rs0 = 0.f, rs1 = 0.f;
#pragma unroll
        for (int nf = 0; nf < 8; nf++) {
            float p0 = __expf(s[nf][0] - mn0);
            float p1 = __expf(s[nf][1] - mn0);
            float p2 = __expf(s[nf][2] - mn1);
            float p3 = __expf(s[nf][3] - mn1);
            rs0 += p0 + p1; rs1 += p2 + p3;
            s[nf][0] = p0; s[nf][1] = p1; s[nf][2] = p2; s[nf][3] = p3;
        }
#pragma unroll
        for (int off = 1; off <= 2; off <<= 1) {
            rs0 += __shfl_xor_sync(0xffffffffu, rs0, off);
            rs1 += __shfl_xor_sync(0xffffffffu, rs1, off);
        }
        l0 = l0 * al0 + rs0;
        l1 = l1 * al1 + rs1;
#pragma unroll
        for (int nf = 0; nf < 16; nf++) {
            o[nf][0] *= al0; o[nf][1] *= al0;
            o[nf][2] *= al1; o[nf][3] *= al1;
        }

        // ---- O += P . V (P packed to A-frags; V B-frags via ldmatrix.trans) ----
#pragma unroll
        for (int kc = 0; kc < 4; kc++) {
            unsigned pa[4];
            pa[0] = pack_h2(s[2*kc][0],     s[2*kc][1]);
            pa[1] = pack_h2(s[2*kc][2],     s[2*kc][3]);
            pa[2] = pack_h2(s[2*kc + 1][0], s[2*kc + 1][1]);
            pa[3] = pack_h2(s[2*kc + 1][2], s[2*kc + 1][3]);
#pragma unroll
            for (int nfp = 0; nfp < 8; nfp++) {
                unsigned b0, b1, b2, b3;
                ldsm4t(b0, b1, b2, b3, vbl + kc * (16 * AT_ROWB) + nfp * 32);
                unsigned bl[2] = { b0, b1 };
                unsigned bh2[2] = { b2, b3 };
                mma_f16(o[2*nfp],     pa, bl);
                mma_f16(o[2*nfp + 1], pa, bh2);
            }
        }
        __syncthreads();
    }

    // ---- epilogue: /l, store f32 ----
    float inv0 = 1.0f / l0, inv1 = 1.0f / l1;
    float* op0 = O + ((size_t)b*T_ + r0g) * QCOLS_ + (size_t)h*HD_;
    float* op1 = O + ((size_t)b*T_ + r1g) * QCOLS_ + (size_t)h*HD_;
#pragma unroll
    for (int nf = 0; nf < 16; nf++) {
        int col = 8 * nf + 2 * m4;
        *(float2*)(op0 + col) = make_float2(o[nf][0] * inv0, o[nf][1] * inv0);
        *(float2*)(op1 + col) = make_float2(o[nf][2] * inv1, o[nf][3] * inv1);
    }
}

// ============================================================================
// launch
// ============================================================================
extern "C" void kernel_launch(void* const* d_in, const int* in_sizes, int n_in,
                              void* d_out, int out_size)
{
    const float* x  = (const float*)d_in[0];
    const float* wq = (const float*)d_in[1];
    const float* wk = (const float*)d_in[2];
    const float* wv = (const float*)d_in[3];
    const float* wo = (const float*)d_in[4];
    const float* qg = (const float*)d_in[5];
    const float* kg = (const float*)d_in[6];
    float* out = (float*)d_out;

    float *q, *k, *v, *o;
    cudaGetSymbolAddress((void**)&q, g_q);
    cudaGetSymbolAddress((void**)&k, g_k);
    cudaGetSymbolAddress((void**)&v, g_v);
    cudaGetSymbolAddress((void**)&o, g_o);

    static bool attr_set = false;
    if (!attr_set) {
        cudaFuncSetAttribute(gemm_f16, cudaFuncAttributeMaxDynamicSharedMemorySize, GEMM_SMEM);
        cudaFuncSetAttribute(attn_f16, cudaFuncAttributeMaxDynamicSharedMemorySize, ATTN_SMEM);
        attr_set = true;
    }

    // projections (fp16 mma, fp32 accumulate)
    gemm_f16<<<dim3(QCOLS_/128, BT_/128), 256, GEMM_SMEM>>>(x, wq, q, BT_, QCOLS_, D_);
    gemm_f16<<<dim3(KCOLS_/128, BT_/128), 256, GEMM_SMEM>>>(x, wk, k, BT_, KCOLS_, D_);
    gemm_f16<<<dim3(KCOLS_/128, BT_/128), 256, GEMM_SMEM>>>(x, wv, v, BT_, KCOLS_, D_);

    // QK-norm (fold attention scale into q)
    rmsnorm_k<<<(BT_*H_)/8, 256>>>(q, qg, BT_*H_, SCALE_);
    rmsnorm_k<<<(BT_*KVH_)/8, 256>>>(k, kg, BT_*KVH_, 1.0f);

    // attention (fp16 mma + ldmatrix)
    attn_f16<<<dim3(T_/64, B_*H_), 128, ATTN_SMEM>>>(q, k, v, o);

    // output projection
    gemm_f16<<<dim3(D_/128, BT_/128), 256, GEMM_SMEM>>>(o, wo, out, BT_, D_, D_);
}

// round 14
// speedup vs baseline: 2.1119x; 1.1311x over previous
#include <cuda_runtime.h>
#include <cuda_fp16.h>
#include <math.h>
#include <stdint.h>

// ---- problem constants ----
#define D_   2048
#define H_   16
#define KVH_ 4
#define HD_  128
#define B_   2
#define T_   2048
#define BT_  (B_*T_)          // 4096
#define QCOLS_ (H_*HD_)       // 2048
#define KCOLS_ (KVH_*HD_)     // 512
#define CAP_ 50.0f
#define SCALE_ 0.08838834764831845f  // 128^-0.5

// ---- scratch (static device arrays; no allocations allowed) ----
static __device__ float  g_q[BT_*QCOLS_];      // q proj (f32, pre-norm)
static __device__ float  g_k[BT_*KCOLS_];      // k proj (f32, pre-norm)
static __device__ __half g_xh[BT_*D_];         // half copies of GEMM operands
static __device__ __half g_wqh[QCOLS_*D_];
static __device__ __half g_wkh[KCOLS_*D_];
static __device__ __half g_wvh[KCOLS_*D_];
static __device__ __half g_woh[D_*QCOLS_];
static __device__ __half g_qh[BT_*QCOLS_];     // post-norm half q
static __device__ __half g_kh[BT_*KCOLS_];     // post-norm half k
static __device__ __half g_vh[BT_*KCOLS_];     // v (half, direct from GEMM)
static __device__ __half g_oh[BT_*QCOLS_];     // attention out (half)

// ============================================================================
// helpers
// ============================================================================
__device__ __forceinline__ unsigned pack_h2(float lo, float hi) {
    unsigned u;
    asm("cvt.rn.f16x2.f32 %0, %1, %2;" : "=r"(u) : "f"(hi), "f"(lo));
    return u;
}

__device__ __forceinline__ void mma_f16(float* c, const unsigned* a, const unsigned* b) {
    asm volatile(
        "mma.sync.aligned.m16n8k16.row.col.f32.f16.f16.f32 "
        "{%0,%1,%2,%3}, {%4,%5,%6,%7}, {%8,%9}, {%0,%1,%2,%3};"
        : "+f"(c[0]), "+f"(c[1]), "+f"(c[2]), "+f"(c[3])
        : "r"(a[0]), "r"(a[1]), "r"(a[2]), "r"(a[3]), "r"(b[0]), "r"(b[1]));
}

__device__ __forceinline__ void ldsm4(unsigned& r0, unsigned& r1, unsigned& r2, unsigned& r3,
                                      unsigned addr) {
    asm volatile("ldmatrix.sync.aligned.m8n8.x4.shared.b16 {%0,%1,%2,%3}, [%4];"
        : "=r"(r0), "=r"(r1), "=r"(r2), "=r"(r3) : "r"(addr));
}

__device__ __forceinline__ void ldsm4t(unsigned& r0, unsigned& r1, unsigned& r2, unsigned& r3,
                                       unsigned addr) {
    asm volatile("ldmatrix.sync.aligned.m8n8.x4.trans.shared.b16 {%0,%1,%2,%3}, [%4];"
        : "=r"(r0), "=r"(r1), "=r"(r2), "=r"(r3) : "r"(addr));
}

__device__ __forceinline__ float tanh_fast(float x) {
    float r;
    asm("tanh.approx.f32 %0, %1;" : "=f"(r) : "f"(x));
    return r;
}

__device__ __forceinline__ void cp_async16s(unsigned saddr, const void* gsrc) {
    asm volatile("cp.async.cg.shared.global [%0], [%1], 16;" :: "r"(saddr), "l"(gsrc));
}
#define CP_COMMIT() asm volatile("cp.async.commit_group;")
#define CP_WAIT0()  asm volatile("cp.async.wait_group 0;")

// ============================================================================
// f32 -> f16 elementwise (4 floats per thread)
// ============================================================================
__global__ __launch_bounds__(256) void cvt_h(
    const float* __restrict__ in, __half* __restrict__ out, int n4)
{
    int i = blockIdx.x * 256 + threadIdx.x;
    if (i >= n4) return;
    float4 v = ((const float4*)in)[i];
    uint2 u;
    u.x = pack_h2(v.x, v.y);
    u.y = pack_h2(v.z, v.w);
    ((uint2*)out)[i] = u;
}

// ============================================================================
// fp16 GEMM v3: C[M,N] = A[M,K]*B[N,K]^T, A/B half in global. 128x128x64 tiles,
// 256 thr, 8 warps (4x2), warp 32x64. half smem rows padded to 144B
// (ldmatrix conflict-free: (9r+u) mod 8 bijective). 2-stage cp.async.
// Fragments via ldmatrix.x4 (2 A + 4 B per k16-step). HOUT: store half C.
// ============================================================================
#define GBK 64
#define GROWB 144                       // bytes per 64-half row (72 halfs)
#define GSTG (128*GROWB*2)              // A+B per stage = 36864 B
#define GEMMH_SMEM (2*GSTG)             // 73728 B

template<bool HOUT>
__global__ __launch_bounds__(256) void gemm_h(
    const __half* __restrict__ A, const __half* __restrict__ Bw,
    void* __restrict__ Cv, int M, int N, int K)
{
    extern __shared__ char gsm[];
    const unsigned sb = (unsigned)__cvta_generic_to_shared(gsm);

    const int tid  = threadIdx.x;
    const int lane = tid & 31;
    const int warp = tid >> 5;
    const int gid  = lane >> 2, m4 = lane & 3;
    const int wm = (warp & 3) * 32;
    const int wn = (warp >> 2) * 64;
    const int rowBase = blockIdx.y * 128;
    const int colBase = blockIdx.x * 128;

    float acc[2][8][4];
#pragma unroll
    for (int mi = 0; mi < 2; mi++)
#pragma unroll
        for (int ni = 0; ni < 8; ni++)
#pragma unroll
            for (int q = 0; q < 4; q++) acc[mi][ni][q] = 0.f;

    const int nt = K / GBK;

    auto load_stage = [&](int st, int k0) {
        unsigned base = sb + st * GSTG;
#pragma unroll
        for (int it = 0; it < 4; it++) {
            int ci = it * 256 + tid;
            int r = ci >> 3, c = ci & 7;
            cp_async16s(base + r * GROWB + c * 16,
                        A + (size_t)(rowBase + r) * K + k0 + c * 8);
            cp_async16s(base + 128 * GROWB + r * GROWB + c * 16,
                        Bw + (size_t)(colBase + r) * K + k0 + c * 8);
        }
        CP_COMMIT();
    };

    load_stage(0, 0);

    // lane-invariant ldmatrix bases (offsets added per stage)
    const unsigned abo = (wm + ((lane >> 3) & 1) * 8 + (lane & 7)) * GROWB + (lane >> 4) * 16;
    const unsigned bbo = 128 * GROWB + (wn + (lane >> 4) * 8 + (lane & 7)) * GROWB
                       + ((lane >> 3) & 1) * 16;

    int cur = 0;
    for (int t = 0; t < nt; t++) {
        CP_WAIT0();
        __syncthreads();

        if (t + 1 < nt) load_stage(cur ^ 1, (t + 1) * GBK);

        const unsigned ab = sb + cur * GSTG + abo;
        const unsigned bb = sb + cur * GSTG + bbo;
#pragma unroll
        for (int ks = 0; ks < 4; ks++) {
            unsigned a0[4], a1[4];
            ldsm4(a0[0], a0[1], a0[2], a0[3], ab + ks * 32);
            ldsm4(a1[0], a1[1], a1[2], a1[3], ab + 16 * GROWB + ks * 32);
#pragma unroll
            for (int nfp = 0; nfp < 4; nfp++) {
                unsigned b0, b1, b2, b3;
                ldsm4(b0, b1, b2, b3, bb + nfp * (16 * GROWB) + ks * 32);
                unsigned bl[2] = { b0, b1 };
                unsigned bh2[2] = { b2, b3 };
                mma_f16(acc[0][2*nfp],     a0, bl);
                mma_f16(acc[0][2*nfp + 1], a0, bh2);
                mma_f16(acc[1][2*nfp],     a1, bl);
                mma_f16(acc[1][2*nfp + 1], a1, bh2);
            }
        }
        cur ^= 1;
    }

    // ---- epilogue ----
#pragma unroll
    for (int mi = 0; mi < 2; mi++) {
        int r0 = rowBase + wm + 16 * mi + gid;
#pragma unroll
        for (int ni = 0; ni < 8; ni++) {
            int c0 = colBase + wn + ni * 8 + m4 * 2;
            if (HOUT) {
                __half* C = (__half*)Cv;
                *(unsigned*)(C + (size_t)r0       * N + c0) = pack_h2(acc[mi][ni][0], acc[mi][ni][1]);
                *(unsigned*)(C + (size_t)(r0 + 8) * N + c0) = pack_h2(acc[mi][ni][2], acc[mi][ni][3]);
            } else {
                float* C = (float*)Cv;
                *(float2*)(C + (size_t)r0       * N + c0) = make_float2(acc[mi][ni][0], acc[mi][ni][1]);
                *(float2*)(C + (size_t)(r0 + 8) * N + c0) = make_float2(acc[mi][ni][2], acc[mi][ni][3]);
            }
        }
    }
}

// ============================================================================
// RMSNorm: f32 in, half out. One warp per 128-elem row. Scale folded (q).
// ============================================================================
__global__ __launch_bounds__(256) void rmsnorm_cvt(
    const float* __restrict__ in, __half* __restrict__ out,
    const float* __restrict__ gamma, int nrows, float scale)
{
    int row  = blockIdx.x * 8 + (threadIdx.x >> 5);
    int lane = threadIdx.x & 31;
    if (row >= nrows) return;
    float4 v = ((const float4*)in)[(size_t)row * 32 + lane];
    float ss = v.x*v.x + v.y*v.y + v.z*v.z + v.w*v.w;
#pragma unroll
    for (int off = 16; off > 0; off >>= 1)
        ss += __shfl_xor_sync(0xffffffffu, ss, off);
    float r = rsqrtf(ss * (1.0f/128.0f) + 1e-6f) * scale;
    float4 g = ((const float4*)gamma)[lane];
    uint2 u;
    u.x = pack_h2(v.x * r * g.x, v.y * r * g.y);
    u.y = pack_h2(v.z * r * g.z, v.w * r * g.w);
    ((uint2*)(out + (size_t)row * 128))[lane] = u;
}

// ============================================================================
// fp16 flash attention (R12 compute path; cp.async half tile loads; half out).
// CTA: 128 thr (4 warps), tile 64q x 64k, HD=128, smem half [64][136].
// ============================================================================
#define AT_LDH 136
#define AT_ROWB (AT_LDH*2)               // 272 B per row
#define ATTN_SMEM (3 * 64 * AT_ROWB)     // 52224 B

__global__ __launch_bounds__(128) void attn_f16(
    const __half* __restrict__ Q, const __half* __restrict__ Kk,
    const __half* __restrict__ Vv, __half* __restrict__ O)
{
    extern __shared__ char smc[];
    const unsigned qs_b = (unsigned)__cvta_generic_to_shared(smc);
    const unsigned ks_b = qs_b + 64 * AT_ROWB;
    const unsigned vs_b = ks_b + 64 * AT_ROWB;

    const int tid  = threadIdx.x;
    const int lane = tid & 31;
    const int warp = tid >> 5;
    const int gid  = lane >> 2;
    const int m4   = lane & 3;

    const int bh = blockIdx.y;
    const int b = bh >> 4, h = bh & 15, kvh = h >> 2;
    const int qt = gridDim.x - 1 - blockIdx.x;     // heavy tiles first
    const int qBase = qt * 64;

    const __half* qp = Q  + (size_t)b*T_*QCOLS_ + (size_t)h*HD_;
    const __half* kp = Kk + (size_t)b*T_*KCOLS_ + (size_t)kvh*HD_;
    const __half* vp = Vv + (size_t)b*T_*KCOLS_ + (size_t)kvh*HD_;

    // ---- load Q tile via cp.async (64 rows x 128 halfs = 8 chunks/thread) ----
#pragma unroll
    for (int it = 0; it < 8; it++) {
        int ci = it * 128 + tid;
        int r = ci >> 4, c = ci & 15;
        cp_async16s(qs_b + r * AT_ROWB + c * 16,
                    qp + (size_t)(qBase + r) * QCOLS_ + c * 8);
    }
    CP_COMMIT();
    CP_WAIT0();
    __syncthreads();

    // ---- hoist Q A-fragments (once per CTA) ----
    unsigned qa[8][4];
    {
        unsigned qrow = 16 * warp + ((lane >> 3) & 1) * 8 + (lane & 7);
        unsigned qbase = qs_b + qrow * AT_ROWB + (lane >> 4) * 16;
#pragma unroll
        for (int kc = 0; kc < 8; kc++)
            ldsm4(qa[kc][0], qa[kc][1], qa[kc][2], qa[kc][3], qbase + kc * 32);
    }

    const unsigned kbl = ks_b + ((lane >> 4) * 8 + (lane & 7)) * AT_ROWB + ((lane >> 3) & 1) * 16;
    const unsigned vbl = vs_b + (((lane >> 3) & 1) * 8 + (lane & 7)) * AT_ROWB + (lane >> 4) * 16;

    float m0 = -INFINITY, m1 = -INFINITY, l0 = 0.f, l1 = 0.f;
    float o[16][4];
#pragma unroll
    for (int nf = 0; nf < 16; nf++)
#pragma unroll
        for (int q = 0; q < 4; q++) o[nf][q] = 0.f;

    const int r0g = qBase + 16 * warp + gid;
    const int r1g = r0g + 8;

    for (int jt = 0; jt <= qt; jt++) {
        const int kBase = jt * 64;

        // ---- load K, V tiles via cp.async ----
#pragma unroll
        for (int it = 0; it < 8; it++) {
            int ci = it * 128 + tid;
            int r = ci >> 4, c = ci & 15;
            cp_async16s(ks_b + r * AT_ROWB + c * 16,
                        kp + (size_t)(kBase + r) * KCOLS_ + c * 8);
            cp_async16s(vs_b + r * AT_ROWB + c * 16,
                        vp + (size_t)(kBase + r) * KCOLS_ + c * 8);
        }
        CP_COMMIT();
        CP_WAIT0();
        __syncthreads();

        // ---- S = Q . K^T ----
        float s[8][4];
#pragma unroll
        for (int nf = 0; nf < 8; nf++)
#pragma unroll
            for (int q = 0; q < 4; q++) s[nf][q] = 0.f;

#pragma unroll
        for (int kc = 0; kc < 8; kc++) {
#pragma unroll
            for (int nfp = 0; nfp < 4; nfp++) {
                unsigned b0, b1, b2, b3;
                ldsm4(b0, b1, b2, b3, kbl + nfp * (16 * AT_ROWB) + kc * 32);
                unsigned bl[2] = { b0, b1 };
                unsigned bh2[2] = { b2, b3 };
                mma_f16(s[2*nfp],     qa[kc], bl);
                mma_f16(s[2*nfp + 1], qa[kc], bh2);
            }
        }

        // ---- softcap + causal mask ----
        const int cb = kBase + 2 * m4;
#pragma unroll
        for (int nf = 0; nf < 8; nf++) {
#pragma unroll
            for (int q = 0; q < 4; q++) {
                int col = cb + 8 * nf + (q & 1);
                int row = (q < 2) ? r0g : r1g;
                float val = CAP_ * tanh_fast(s[nf][q] * (1.0f / CAP_));
                s[nf][q] = (col > row) ? -INFINITY : val;
            }
        }

        // ---- online softmax ----
        float rmax0 = -INFINITY, rmax1 = -INFINITY;
#pragma unroll
        for (int nf = 0; nf < 8; nf++) {
            rmax0 = fmaxf(rmax0, fmaxf(s[nf][0], s[nf][1]));
            rmax1 = fmaxf(rmax1, fmaxf(s[nf][2], s[nf][3]));
        }
#pragma unroll
        for (int off = 1; off <= 2; off <<= 1) {
            rmax0 = fmaxf(rmax0, __shfl_xor_sync(0xffffffffu, rmax0, off));
            rmax1 = fmaxf(rmax1, __shfl_xor_sync(0xffffffffu, rmax1, off));
        }
        float mn0 = fmaxf(m0, rmax0), mn1 = fmaxf(m1, rmax1);
        float al0 = __expf(m0 - mn0), al1 = __expf(m1 - mn1);
        m0 = mn0; m1 = mn1;

        float rs0 = 0.f, rs1 = 0.f;
#pragma unroll
        for (int nf = 0; nf < 8; nf++) {
            float p0 = __expf(s[nf][0] - mn0);
            float p1 = __expf(s[nf][1] - mn0);
            float p2 = __expf(s[nf][2] - mn1);
            float p3 = __expf(s[nf][3] - mn1);
            rs0 += p0 + p1; rs1 += p2 + p3;
            s[nf][0] = p0; s[nf][1] = p1; s[nf][2] = p2; s[nf][3] = p3;
        }
#pragma unroll
        for (int off = 1; off <= 2; off <<= 1) {
            rs0 += __shfl_xor_sync(0xffffffffu, rs0, off);
            rs1 += __shfl_xor_sync(0xffffffffu, rs1, off);
        }
        l0 = l0 * al0 + rs0;
        l1 = l1 * al1 + rs1;
#pragma unroll
        for (int nf = 0; nf < 16; nf++) {
            o[nf][0] *= al0; o[nf][1] *= al0;
            o[nf][2] *= al1; o[nf][3] *= al1;
        }

        // ---- O += P . V ----
#pragma unroll
        for (int kc = 0; kc < 4; kc++) {
            unsigned pa[4];
            pa[0] = pack_h2(s[2*kc][0],     s[2*kc][1]);
            pa[1] = pack_h2(s[2*kc][2],     s[2*kc][3]);
            pa[2] = pack_h2(s[2*kc + 1][0], s[2*kc + 1][1]);
            pa[3] = pack_h2(s[2*kc + 1][2], s[2*kc + 1][3]);
#pragma unroll
            for (int nfp = 0; nfp < 8; nfp++) {
                unsigned b0, b1, b2, b3;
                ldsm4t(b0, b1, b2, b3, vbl + kc * (16 * AT_ROWB) + nfp * 32);
                unsigned bl[2] = { b0, b1 };
                unsigned bh2[2] = { b2, b3 };
                mma_f16(o[2*nfp],     pa, bl);
                mma_f16(o[2*nfp + 1], pa, bh2);
            }
        }
        __syncthreads();
    }

    // ---- epilogue: /l, store half ----
    float inv0 = 1.0f / l0, inv1 = 1.0f / l1;
    __half* op0 = O + ((size_t)b*T_ + r0g) * QCOLS_ + (size_t)h*HD_;
    __half* op1 = O + ((size_t)b*T_ + r1g) * QCOLS_ + (size_t)h*HD_;
#pragma unroll
    for (int nf = 0; nf < 16; nf++) {
        int col = 8 * nf + 2 * m4;
        *(unsigned*)(op0 + col) = pack_h2(o[nf][0] * inv0, o[nf][1] * inv0);
        *(unsigned*)(op1 + col) = pack_h2(o[nf][2] * inv1, o[nf][3] * inv1);
    }
}

// ============================================================================
// launch
// ============================================================================
extern "C" void kernel_launch(void* const* d_in, const int* in_sizes, int n_in,
                              void* d_out, int out_size)
{
    const float* x  = (const float*)d_in[0];
    const float* wq = (const float*)d_in[1];
    const float* wk = (const float*)d_in[2];
    const float* wv = (const float*)d_in[3];
    const float* wo = (const float*)d_in[4];
    const float* qg = (const float*)d_in[5];
    const float* kg = (const float*)d_in[6];
    float* out = (float*)d_out;

    float *q, *k;
    __half *xh, *wqh, *wkh, *wvh, *woh, *qh, *kh, *vh, *oh;
    cudaGetSymbolAddress((void**)&q,   g_q);
    cudaGetSymbolAddress((void**)&k,   g_k);
    cudaGetSymbolAddress((void**)&xh,  g_xh);
    cudaGetSymbolAddress((void**)&wqh, g_wqh);
    cudaGetSymbolAddress((void**)&wkh, g_wkh);
    cudaGetSymbolAddress((void**)&wvh, g_wvh);
    cudaGetSymbolAddress((void**)&woh, g_woh);
    cudaGetSymbolAddress((void**)&qh,  g_qh);
    cudaGetSymbolAddress((void**)&kh,  g_kh);
    cudaGetSymbolAddress((void**)&vh,  g_vh);
    cudaGetSymbolAddress((void**)&oh,  g_oh);

    static bool attr_set = false;
    if (!attr_set) {
        cudaFuncSetAttribute(gemm_h<false>, cudaFuncAttributeMaxDynamicSharedMemorySize, GEMMH_SMEM);
        cudaFuncSetAttribute(gemm_h<true>,  cudaFuncAttributeMaxDynamicSharedMemorySize, GEMMH_SMEM);
        cudaFuncSetAttribute(attn_f16, cudaFuncAttributeMaxDynamicSharedMemorySize, ATTN_SMEM);
        attr_set = true;
    }

    // one-shot f32 -> f16 operand conversion
    cvt_h<<<(BT_*D_/4 + 255)/256, 256>>>(x,  xh,  BT_*D_/4);
    cvt_h<<<(QCOLS_*D_/4 + 255)/256, 256>>>(wq, wqh, QCOLS_*D_/4);
    cvt_h<<<(KCOLS_*D_/4 + 255)/256, 256>>>(wk, wkh, KCOLS_*D_/4);
    cvt_h<<<(KCOLS_*D_/4 + 255)/256, 256>>>(wv, wvh, KCOLS_*D_/4);
    cvt_h<<<(D_*QCOLS_/4 + 255)/256, 256>>>(wo, woh, D_*QCOLS_/4);

    // projections (fp16 ldmatrix GEMM): q,k -> f32 (pre-norm), v -> half
    gemm_h<false><<<dim3(QCOLS_/128, BT_/128), 256, GEMMH_SMEM>>>(xh, wqh, q,  BT_, QCOLS_, D_);
    gemm_h<false><<<dim3(KCOLS_/128, BT_/128), 256, GEMMH_SMEM>>>(xh, wkh, k,  BT_, KCOLS_, D_);
    gemm_h<true ><<<dim3(KCOLS_/128, BT_/128), 256, GEMMH_SMEM>>>(xh, wvh, vh, BT_, KCOLS_, D_);

    // QK-norm: f32 in, half out (scale folded into q)
    rmsnorm_cvt<<<(BT_*H_)/8, 256>>>(q, qh, qg, BT_*H_, SCALE_);
    rmsnorm_cvt<<<(BT_*KVH_)/8, 256>>>(k, kh, kg, BT_*KVH_, 1.0f);

    // attention (fp16 mma + ldmatrix; half in, half out)
    attn_f16<<<dim3(T_/64, B_*H_), 128, ATTN_SMEM>>>(qh, kh, vh, oh);

    // output projection (half in, f32 out)
    gemm_h<false><<<dim3(D_/128, BT_/128), 256, GEMMH_SMEM>>>(oh, woh, out, BT_, D_, D_);
}

// round 15
// speedup vs baseline: 3.1553x; 1.4941x over previous
#include <cuda_runtime.h>
#include <cuda_fp16.h>
#include <math.h>
#include <stdint.h>

// ---- problem constants ----
#define D_   2048
#define H_   16
#define KVH_ 4
#define HD_  128
#define B_   2
#define T_   2048
#define BT_  (B_*T_)          // 4096
#define QCOLS_ (H_*HD_)       // 2048
#define KCOLS_ (KVH_*HD_)     // 512
#define CAP_ 50.0f
#define SCALE_ 0.08838834764831845f  // 128^-0.5

// ---- scratch (static device arrays; no allocations allowed) ----
static __device__ float  g_q[BT_*QCOLS_];      // q proj (f32, pre-norm)
static __device__ float  g_k[BT_*KCOLS_];      // k proj (f32, pre-norm)
static __device__ __half g_xh[BT_*D_];         // half copies of GEMM operands
static __device__ __half g_wqh[QCOLS_*D_];
static __device__ __half g_wkh[KCOLS_*D_];
static __device__ __half g_wvh[KCOLS_*D_];
static __device__ __half g_woh[D_*QCOLS_];
static __device__ __half g_qh[BT_*QCOLS_];     // post-norm half q
static __device__ __half g_kh[BT_*KCOLS_];     // post-norm half k
static __device__ __half g_vh[BT_*KCOLS_];     // v (half, direct from GEMM)
static __device__ __half g_oh[BT_*QCOLS_];     // attention out (half)

// ============================================================================
// helpers
// ============================================================================
__device__ __forceinline__ unsigned pack_h2(float lo, float hi) {
    unsigned u;
    asm("cvt.rn.f16x2.f32 %0, %1, %2;" : "=r"(u) : "f"(hi), "f"(lo));
    return u;
}

__device__ __forceinline__ void mma_f16(float* c, const unsigned* a, const unsigned* b) {
    asm volatile(
        "mma.sync.aligned.m16n8k16.row.col.f32.f16.f16.f32 "
        "{%0,%1,%2,%3}, {%4,%5,%6,%7}, {%8,%9}, {%0,%1,%2,%3};"
        : "+f"(c[0]), "+f"(c[1]), "+f"(c[2]), "+f"(c[3])
        : "r"(a[0]), "r"(a[1]), "r"(a[2]), "r"(a[3]), "r"(b[0]), "r"(b[1]));
}

__device__ __forceinline__ void ldsm4(unsigned& r0, unsigned& r1, unsigned& r2, unsigned& r3,
                                      unsigned addr) {
    asm volatile("ldmatrix.sync.aligned.m8n8.x4.shared.b16 {%0,%1,%2,%3}, [%4];"
        : "=r"(r0), "=r"(r1), "=r"(r2), "=r"(r3) : "r"(addr));
}

__device__ __forceinline__ void ldsm4t(unsigned& r0, unsigned& r1, unsigned& r2, unsigned& r3,
                                       unsigned addr) {
    asm volatile("ldmatrix.sync.aligned.m8n8.x4.trans.shared.b16 {%0,%1,%2,%3}, [%4];"
        : "=r"(r0), "=r"(r1), "=r"(r2), "=r"(r3) : "r"(addr));
}

__device__ __forceinline__ float tanh_fast(float x) {
    float r;
    asm("tanh.approx.f32 %0, %1;" : "=f"(r) : "f"(x));
    return r;
}

__device__ __forceinline__ void cp_async16s(unsigned saddr, const void* gsrc) {
    asm volatile("cp.async.cg.shared.global [%0], [%1], 16;" :: "r"(saddr), "l"(gsrc));
}
#define CP_COMMIT() asm volatile("cp.async.commit_group;")
#define CP_WAIT0()  asm volatile("cp.async.wait_group 0;")

// ============================================================================
// f32 -> f16 elementwise (4 floats per thread)
// ============================================================================
__global__ __launch_bounds__(256) void cvt_h(
    const float* __restrict__ in, __half* __restrict__ out, int n4)
{
    int i = blockIdx.x * 256 + threadIdx.x;
    if (i >= n4) return;
    float4 v = ((const float4*)in)[i];
    uint2 u;
    u.x = pack_h2(v.x, v.y);
    u.y = pack_h2(v.z, v.w);
    ((uint2*)out)[i] = u;
}

// ============================================================================
// fp16 GEMM (R14, unchanged): 128x128x64 tiles, 256 thr, 8 warps, ldmatrix,
// 2-stage cp.async, 144B row pad (conflict-free ldmatrix phases).
// ============================================================================
#define GBK 64
#define GROWB 144
#define GSTG (128*GROWB*2)
#define GEMMH_SMEM (2*GSTG)

template<bool HOUT>
__global__ __launch_bounds__(256) void gemm_h(
    const __half* __restrict__ A, const __half* __restrict__ Bw,
    void* __restrict__ Cv, int M, int N, int K)
{
    extern __shared__ char gsm[];
    const unsigned sb = (unsigned)__cvta_generic_to_shared(gsm);

    const int tid  = threadIdx.x;
    const int lane = tid & 31;
    const int warp = tid >> 5;
    const int gid  = lane >> 2, m4 = lane & 3;
    const int wm = (warp & 3) * 32;
    const int wn = (warp >> 2) * 64;
    const int rowBase = blockIdx.y * 128;
    const int colBase = blockIdx.x * 128;

    float acc[2][8][4];
#pragma unroll
    for (int mi = 0; mi < 2; mi++)
#pragma unroll
        for (int ni = 0; ni < 8; ni++)
#pragma unroll
            for (int q = 0; q < 4; q++) acc[mi][ni][q] = 0.f;

    const int nt = K / GBK;

    auto load_stage = [&](int st, int k0) {
        unsigned base = sb + st * GSTG;
#pragma unroll
        for (int it = 0; it < 4; it++) {
            int ci = it * 256 + tid;
            int r = ci >> 3, c = ci & 7;
            cp_async16s(base + r * GROWB + c * 16,
                        A + (size_t)(rowBase + r) * K + k0 + c * 8);
            cp_async16s(base + 128 * GROWB + r * GROWB + c * 16,
                        Bw + (size_t)(colBase + r) * K + k0 + c * 8);
        }
        CP_COMMIT();
    };

    load_stage(0, 0);

    const unsigned abo = (wm + ((lane >> 3) & 1) * 8 + (lane & 7)) * GROWB + (lane >> 4) * 16;
    const unsigned bbo = 128 * GROWB + (wn + (lane >> 4) * 8 + (lane & 7)) * GROWB
                       + ((lane >> 3) & 1) * 16;

    int cur = 0;
    for (int t = 0; t < nt; t++) {
        CP_WAIT0();
        __syncthreads();

        if (t + 1 < nt) load_stage(cur ^ 1, (t + 1) * GBK);

        const unsigned ab = sb + cur * GSTG + abo;
        const unsigned bb = sb + cur * GSTG + bbo;
#pragma unroll
        for (int ks = 0; ks < 4; ks++) {
            unsigned a0[4], a1[4];
            ldsm4(a0[0], a0[1], a0[2], a0[3], ab + ks * 32);
            ldsm4(a1[0], a1[1], a1[2], a1[3], ab + 16 * GROWB + ks * 32);
#pragma unroll
            for (int nfp = 0; nfp < 4; nfp++) {
                unsigned b0, b1, b2, b3;
                ldsm4(b0, b1, b2, b3, bb + nfp * (16 * GROWB) + ks * 32);
                unsigned bl[2] = { b0, b1 };
                unsigned bh2[2] = { b2, b3 };
                mma_f16(acc[0][2*nfp],     a0, bl);
                mma_f16(acc[0][2*nfp + 1], a0, bh2);
                mma_f16(acc[1][2*nfp],     a1, bl);
                mma_f16(acc[1][2*nfp + 1], a1, bh2);
            }
        }
        cur ^= 1;
    }

#pragma unroll
    for (int mi = 0; mi < 2; mi++) {
        int r0 = rowBase + wm + 16 * mi + gid;
#pragma unroll
        for (int ni = 0; ni < 8; ni++) {
            int c0 = colBase + wn + ni * 8 + m4 * 2;
            if (HOUT) {
                __half* C = (__half*)Cv;
                *(unsigned*)(C + (size_t)r0       * N + c0) = pack_h2(acc[mi][ni][0], acc[mi][ni][1]);
                *(unsigned*)(C + (size_t)(r0 + 8) * N + c0) = pack_h2(acc[mi][ni][2], acc[mi][ni][3]);
            } else {
                float* C = (float*)Cv;
                *(float2*)(C + (size_t)r0       * N + c0) = make_float2(acc[mi][ni][0], acc[mi][ni][1]);
                *(float2*)(C + (size_t)(r0 + 8) * N + c0) = make_float2(acc[mi][ni][2], acc[mi][ni][3]);
            }
        }
    }
}

// ============================================================================
// RMSNorm: f32 in, half out. One warp per 128-elem row. Scale folded (q).
// ============================================================================
__global__ __launch_bounds__(256) void rmsnorm_cvt(
    const float* __restrict__ in, __half* __restrict__ out,
    const float* __restrict__ gamma, int nrows, float scale)
{
    int row  = blockIdx.x * 8 + (threadIdx.x >> 5);
    int lane = threadIdx.x & 31;
    if (row >= nrows) return;
    float4 v = ((const float4*)in)[(size_t)row * 32 + lane];
    float ss = v.x*v.x + v.y*v.y + v.z*v.z + v.w*v.w;
#pragma unroll
    for (int off = 16; off > 0; off >>= 1)
        ss += __shfl_xor_sync(0xffffffffu, ss, off);
    float r = rsqrtf(ss * (1.0f/128.0f) + 1e-6f) * scale;
    float4 g = ((const float4*)gamma)[lane];
    uint2 u;
    u.x = pack_h2(v.x * r * g.x, v.y * r * g.y);
    u.y = pack_h2(v.z * r * g.z, v.w * r * g.w);
    ((uint2*)(out + (size_t)row * 128))[lane] = u;
}

// ============================================================================
// fp16 flash attention v4: R14 compute path + DOUBLE-BUFFERED K/V.
// CTA: 128 thr (4 warps), tile 64q x 64k, HD=128, smem half [64][136].
// smem: Q | K0 | V0 | K1 | V1 (5 x 17408 B = 87040 B -> 2 CTAs/SM).
// Loop: wait(jt) -> sync -> issue cp.async(jt+1, other buf) -> compute(jt).
// One barrier per iter; loads fully overlap compute.
// ============================================================================
#define AT_LDH 136
#define AT_ROWB (AT_LDH*2)               // 272 B per row
#define AT_TILE (64*AT_ROWB)             // 17408 B per tile
#define ATTN_SMEM (5*AT_TILE)            // 87040 B

__global__ __launch_bounds__(128) void attn_f16(
    const __half* __restrict__ Q, const __half* __restrict__ Kk,
    const __half* __restrict__ Vv, __half* __restrict__ O)
{
    extern __shared__ char smc[];
    const unsigned qs_b = (unsigned)__cvta_generic_to_shared(smc);

    const int tid  = threadIdx.x;
    const int lane = tid & 31;
    const int warp = tid >> 5;
    const int gid  = lane >> 2;
    const int m4   = lane & 3;

    const int bh = blockIdx.y;
    const int b = bh >> 4, h = bh & 15, kvh = h >> 2;
    const int qt = gridDim.x - 1 - blockIdx.x;     // heavy tiles first
    const int qBase = qt * 64;

    const __half* qp = Q  + (size_t)b*T_*QCOLS_ + (size_t)h*HD_;
    const __half* kp = Kk + (size_t)b*T_*KCOLS_ + (size_t)kvh*HD_;
    const __half* vp = Vv + (size_t)b*T_*KCOLS_ + (size_t)kvh*HD_;

    // K/V stage loader: stage st buffers at qs_b + (1+2*st)*AT_TILE
    auto load_kv = [&](int st, int kBase) {
        unsigned kb = qs_b + (1 + 2 * st) * AT_TILE;
        unsigned vb = kb + AT_TILE;
#pragma unroll
        for (int it = 0; it < 8; it++) {
            int ci = it * 128 + tid;
            int r = ci >> 4, c = ci & 15;
            cp_async16s(kb + r * AT_ROWB + c * 16,
                        kp + (size_t)(kBase + r) * KCOLS_ + c * 8);
            cp_async16s(vb + r * AT_ROWB + c * 16,
                        vp + (size_t)(kBase + r) * KCOLS_ + c * 8);
        }
        CP_COMMIT();
    };

    // ---- load Q tile via cp.async ----
#pragma unroll
    for (int it = 0; it < 8; it++) {
        int ci = it * 128 + tid;
        int r = ci >> 4, c = ci & 15;
        cp_async16s(qs_b + r * AT_ROWB + c * 16,
                    qp + (size_t)(qBase + r) * QCOLS_ + c * 8);
    }
    CP_COMMIT();

    // prologue: K/V stage 0 (separate commit group after Q's)
    load_kv(0, 0);

    CP_WAIT0();
    __syncthreads();

    // ---- hoist Q A-fragments (once per CTA) ----
    unsigned qa[8][4];
    {
        unsigned qrow = 16 * warp + ((lane >> 3) & 1) * 8 + (lane & 7);
        unsigned qbase = qs_b + qrow * AT_ROWB + (lane >> 4) * 16;
#pragma unroll
        for (int kc = 0; kc < 8; kc++)
            ldsm4(qa[kc][0], qa[kc][1], qa[kc][2], qa[kc][3], qbase + kc * 32);
    }

    // lane-invariant ldmatrix offsets within a K/V tile
    const unsigned klo = ((lane >> 4) * 8 + (lane & 7)) * AT_ROWB + ((lane >> 3) & 1) * 16;
    const unsigned vlo = (((lane >> 3) & 1) * 8 + (lane & 7)) * AT_ROWB + (lane >> 4) * 16;

    float m0 = -INFINITY, m1 = -INFINITY, l0 = 0.f, l1 = 0.f;
    float o[16][4];
#pragma unroll
    for (int nf = 0; nf < 16; nf++)
#pragma unroll
        for (int q = 0; q < 4; q++) o[nf][q] = 0.f;

    const int r0g = qBase + 16 * warp + gid;
    const int r1g = r0g + 8;

    for (int jt = 0; jt <= qt; jt++) {
        const int kBase = jt * 64;

        if (jt > 0) { CP_WAIT0(); }
        __syncthreads();          // publishes stage jt; protects buffer (jt+1)&1

        if (jt < qt) load_kv((jt + 1) & 1, kBase + 64);

        const unsigned kbl = qs_b + (1 + 2 * (jt & 1)) * AT_TILE + klo;
        const unsigned vbl = kbl + AT_TILE - klo + vlo;

        // ---- S = Q . K^T ----
        float s[8][4];
#pragma unroll
        for (int nf = 0; nf < 8; nf++)
#pragma unroll
            for (int q = 0; q < 4; q++) s[nf][q] = 0.f;

#pragma unroll
        for (int kc = 0; kc < 8; kc++) {
#pragma unroll
            for (int nfp = 0; nfp < 4; nfp++) {
                unsigned b0, b1, b2, b3;
                ldsm4(b0, b1, b2, b3, kbl + nfp * (16 * AT_ROWB) + kc * 32);
                unsigned bl[2] = { b0, b1 };
                unsigned bh2[2] = { b2, b3 };
                mma_f16(s[2*nfp],     qa[kc], bl);
                mma_f16(s[2*nfp + 1], qa[kc], bh2);
            }
        }

        // ---- softcap + causal mask ----
        const int cb = kBase + 2 * m4;
#pragma unroll
        for (int nf = 0; nf < 8; nf++) {
#pragma unroll
            for (int q = 0; q < 4; q++) {
                int col = cb + 8 * nf + (q & 1);
                int row = (q < 2) ? r0g : r1g;
                float val = CAP_ * tanh_fast(s[nf][q] * (1.0f / CAP_));
                s[nf][q] = (col > row) ? -INFINITY : val;
            }
        }

        // ---- online softmax ----
        float rmax0 = -INFINITY, rmax1 = -INFINITY;
#pragma unroll
        for (int nf = 0; nf < 8; nf++) {
            rmax0 = fmaxf(rmax0, fmaxf(s[nf][0], s[nf][1]));
            rmax1 = fmaxf(rmax1, fmaxf(s[nf][2], s[nf][3]));
        }
#pragma unroll
        for (int off = 1; off <= 2; off <<= 1) {
            rmax0 = fmaxf(rmax0, __shfl_xor_sync(0xffffffffu, rmax0, off));
            rmax1 = fmaxf(rmax1, __shfl_xor_sync(0xffffffffu, rmax1, off));
        }
        float mn0 = fmaxf(m0, rmax0), mn1 = fmaxf(m1, rmax1);
        float al0 = __expf(m0 - mn0), al1 = __expf(m1 - mn1);
        m0 = mn0; m1 = mn1;

        float rs0 = 0.f, rs1 = 0.f;
#pragma unroll
        for (int nf = 0; nf < 8; nf++) {
            float p0 = __expf(s[nf][0] - mn0);
            float p1 = __expf(s[nf][1] - mn0);
            float p2 = __expf(s[nf][2] - mn1);
            float p3 = __expf(s[nf][3] - mn1);
            rs0 += p0 + p1; rs1 += p2 + p3;
            s[nf][0] = p0; s[nf][1] = p1; s[nf][2] = p2; s[nf][3] = p3;
        }
#pragma unroll
        for (int off = 1; off <= 2; off <<= 1) {
            rs0 += __shfl_xor_sync(0xffffffffu, rs0, off);
            rs1 += __shfl_xor_sync(0xffffffffu, rs1, off);
        }
        l0 = l0 * al0 + rs0;
        l1 = l1 * al1 + rs1;
#pragma unroll
        for (int nf = 0; nf < 16; nf++) {
            o[nf][0] *= al0; o[nf][1] *= al0;
            o[nf][2] *= al1; o[nf][3] *= al1;
        }

        // ---- O += P . V ----
#pragma unroll
        for (int kc = 0; kc < 4; kc++) {
            unsigned pa[4];
            pa[0] = pack_h2(s[2*kc][0],     s[2*kc][1]);
            pa[1] = pack_h2(s[2*kc][2],     s[2*kc][3]);
            pa[2] = pack_h2(s[2*kc + 1][0], s[2*kc + 1][1]);
            pa[3] = pack_h2(s[2*kc + 1][2], s[2*kc + 1][3]);
#pragma unroll
            for (int nfp = 0; nfp < 8; nfp++) {
                unsigned b0, b1, b2, b3;
                ldsm4t(b0, b1, b2, b3, vbl + kc * (16 * AT_ROWB) + nfp * 32);
                unsigned bl[2] = { b0, b1 };
                unsigned bh2[2] = { b2, b3 };
                mma_f16(o[2*nfp],     pa, bl);
                mma_f16(o[2*nfp + 1], pa, bh2);
            }
        }
        // no trailing barrier: buffer parity + next-iter sync cover reuse
    }

    // ---- epilogue: /l, store half ----
    float inv0 = 1.0f / l0, inv1 = 1.0f / l1;
    __half* op0 = O + ((size_t)b*T_ + r0g) * QCOLS_ + (size_t)h*HD_;
    __half* op1 = O + ((size_t)b*T_ + r1g) * QCOLS_ + (size_t)h*HD_;
#pragma unroll
    for (int nf = 0; nf < 16; nf++) {
        int col = 8 * nf + 2 * m4;
        *(unsigned*)(op0 + col) = pack_h2(o[nf][0] * inv0, o[nf][1] * inv0);
        *(unsigned*)(op1 + col) = pack_h2(o[nf][2] * inv1, o[nf][3] * inv1);
    }
}

// ============================================================================
// launch
// ============================================================================
extern "C" void kernel_launch(void* const* d_in, const int* in_sizes, int n_in,
                              void* d_out, int out_size)
{
    const float* x  = (const float*)d_in[0];
    const float* wq = (const float*)d_in[1];
    const float* wk = (const float*)d_in[2];
    const float* wv = (const float*)d_in[3];
    const float* wo = (const float*)d_in[4];
    const float* qg = (const float*)d_in[5];
    const float* kg = (const float*)d_in[6];
    float* out = (float*)d_out;

    float *q, *k;
    __half *xh, *wqh, *wkh, *wvh, *woh, *qh, *kh, *vh, *oh;
    cudaGetSymbolAddress((void**)&q,   g_q);
    cudaGetSymbolAddress((void**)&k,   g_k);
    cudaGetSymbolAddress((void**)&xh,  g_xh);
    cudaGetSymbolAddress((void**)&wqh, g_wqh);
    cudaGetSymbolAddress((void**)&wkh, g_wkh);
    cudaGetSymbolAddress((void**)&wvh, g_wvh);
    cudaGetSymbolAddress((void**)&woh, g_woh);
    cudaGetSymbolAddress((void**)&qh,  g_qh);
    cudaGetSymbolAddress((void**)&kh,  g_kh);
    cudaGetSymbolAddress((void**)&vh,  g_vh);
    cudaGetSymbolAddress((void**)&oh,  g_oh);

    static bool attr_set = false;
    if (!attr_set) {
        cudaFuncSetAttribute(gemm_h<false>, cudaFuncAttributeMaxDynamicSharedMemorySize, GEMMH_SMEM);
        cudaFuncSetAttribute(gemm_h<true>,  cudaFuncAttributeMaxDynamicSharedMemorySize, GEMMH_SMEM);
        cudaFuncSetAttribute(attn_f16, cudaFuncAttributeMaxDynamicSharedMemorySize, ATTN_SMEM);
        attr_set = true;
    }

    // one-shot f32 -> f16 operand conversion
    cvt_h<<<(BT_*D_/4 + 255)/256, 256>>>(x,  xh,  BT_*D_/4);
    cvt_h<<<(QCOLS_*D_/4 + 255)/256, 256>>>(wq, wqh, QCOLS_*D_/4);
    cvt_h<<<(KCOLS_*D_/4 + 255)/256, 256>>>(wk, wkh, KCOLS_*D_/4);
    cvt_h<<<(KCOLS_*D_/4 + 255)/256, 256>>>(wv, wvh, KCOLS_*D_/4);
    cvt_h<<<(D_*QCOLS_/4 + 255)/256, 256>>>(wo, woh, D_*QCOLS_/4);

    // projections (fp16 ldmatrix GEMM): q,k -> f32 (pre-norm), v -> half
    gemm_h<false><<<dim3(QCOLS_/128, BT_/128), 256, GEMMH_SMEM>>>(xh, wqh, q,  BT_, QCOLS_, D_);
    gemm_h<false><<<dim3(KCOLS_/128, BT_/128), 256, GEMMH_SMEM>>>(xh, wkh, k,  BT_, KCOLS_, D_);
    gemm_h<true ><<<dim3(KCOLS_/128, BT_/128), 256, GEMMH_SMEM>>>(xh, wvh, vh, BT_, KCOLS_, D_);

    // QK-norm: f32 in, half out (scale folded into q)
    rmsnorm_cvt<<<(BT_*H_)/8, 256>>>(q, qh, qg, BT_*H_, SCALE_);
    rmsnorm_cvt<<<(BT_*KVH_)/8, 256>>>(k, kh, kg, BT_*KVH_, 1.0f);

    // attention (fp16 mma + ldmatrix, double-buffered K/V)
    attn_f16<<<dim3(T_/64, B_*H_), 128, ATTN_SMEM>>>(qh, kh, vh, oh);

    // output projection (half in, f32 out)
    gemm_h<false><<<dim3(D_/128, BT_/128), 256, GEMMH_SMEM>>>(oh, woh, out, BT_, D_, D_);
}